// round 13
// baseline (speedup 1.0000x reference)
#include <cuda_runtime.h>
#include <cuda_fp16.h>
#include <math.h>
#include <stdint.h>

#define BB   2
#define SS   2048
#define HH   16
#define DD   64
#define HID  1024
#define PD   128

// ---------------- scratch (device globals — no allocation allowed) ----------------
__device__ float  g_sp[BB*SS];
__device__ double g_posd[BB*SS];
__device__ __align__(256) float g_cos[BB*SS*32];
__device__ __align__(256) float g_sin[BB*SS*32];
// fp16 operands
__device__ __align__(256) __half g_xh[BB*SS*HID];        // x fp16 (hi)
__device__ __align__(256) __half g_xl[BB*SS*HID];        // x fp16 (lo residual)
__device__ __align__(256) __half g_ah[BB*SS*HID];        // attention out fp16
__device__ __align__(256) __half g_wt[4*HID*HID];        // W^T (n,k) fp16, z = q,k,v,o
__device__ __align__(256) __half g_w1h[PD*HID];          // W1^T (p,d) fp16 hi
__device__ __align__(256) __half g_w1l[PD*HID];          // W1^T (p,d) fp16 lo
__device__ __align__(256) float  g_H[4*BB*SS*PD];        // repo H partials, 4 k-slices
__device__ __align__(256) __half g_q[BB*HH*SS*DD];       // (b,h,s,d), RoPE'd, scaled 0.125*log2e
__device__ __align__(256) __half g_k[BB*HH*SS*DD];       // (b,h,s,d), RoPE'd
__device__ __align__(256) __half g_vt[BB*HH*DD*SS];      // (b,h,d,s)  V^T

// ==================== helpers ====================
__device__ __forceinline__ uint32_t smem_u32(const void* p) {
    uint32_t a;
    asm("{ .reg .u64 t; cvta.to.shared.u64 t, %1; cvt.u32.u64 %0, t; }" : "=r"(a) : "l"(p));
    return a;
}
__device__ __forceinline__ void cp_async16(uint32_t dst, const void* src) {
    asm volatile("cp.async.cg.shared.global [%0], [%1], 16;" :: "r"(dst), "l"(src));
}
__device__ __forceinline__ void cp_commit() {
    asm volatile("cp.async.commit_group;" ::: "memory");
}
__device__ __forceinline__ void ldsm_x4(uint32_t* r, uint32_t addr) {
    asm volatile("ldmatrix.sync.aligned.m8n8.x4.shared.b16 {%0,%1,%2,%3}, [%4];"
                 : "=r"(r[0]), "=r"(r[1]), "=r"(r[2]), "=r"(r[3]) : "r"(addr));
}
__device__ __forceinline__ void mma16816(float* c, const uint32_t* a, uint32_t b0, uint32_t b1) {
    asm volatile(
        "mma.sync.aligned.m16n8k16.row.col.f32.f16.f16.f32 "
        "{%0,%1,%2,%3}, {%4,%5,%6,%7}, {%8,%9}, {%0,%1,%2,%3};"
        : "+f"(c[0]), "+f"(c[1]), "+f"(c[2]), "+f"(c[3])
        : "r"(a[0]), "r"(a[1]), "r"(a[2]), "r"(a[3]), "r"(b0), "r"(b1));
}
// pack two fp32 -> f16x2 (first arg -> low half)
__device__ __forceinline__ uint32_t pack_h(float lo, float hi) {
    uint32_t r;
    asm("cvt.rn.f16x2.f32 %0, %2, %1;" : "=r"(r) : "f"(lo), "f"(hi));
    return r;
}
// fast 2^x on the FMA pipe (no MUFU). x <= 0 in softmax use; clamp for exponent safety.
// 2^f on [0,1) via degree-5 Taylor (coeffs ln2^k/k!), integer part via exponent-bit add.
__device__ __forceinline__ float fexp2(float x) {
    x = fmaxf(x, -80.f);
    float fl = floorf(x);
    float f  = x - fl;
    float p  = fmaf(f, 0.0013333558f, 0.0096181291f);
    p = fmaf(p, f, 0.0555041087f);
    p = fmaf(p, f, 0.2402265070f);
    p = fmaf(p, f, 0.6931471806f);
    p = fmaf(p, f, 1.0f);
    return __int_as_float(__float_as_int(p) + ((int)fl << 23));
}

// ==================== fp32 x -> fp16 hi/lo ====================
__global__ __launch_bounds__(256) void conv_x_kernel(const float* __restrict__ src)
{
    int idx = (blockIdx.x * 256 + threadIdx.x) * 4;
    float4 v = *(const float4*)&src[idx];
    __half hx = __float2half(v.x), hy = __float2half(v.y);
    __half hz = __float2half(v.z), hw = __float2half(v.w);
    uint2 H, L;
    H.x = pack_h(v.x, v.y);
    H.y = pack_h(v.z, v.w);
    L.x = pack_h(v.x - __half2float(hx), v.y - __half2float(hy));
    L.y = pack_h(v.z - __half2float(hz), v.w - __half2float(hw));
    *(uint2*)&g_xh[idx] = H;
    *(uint2*)&g_xl[idx] = L;
}

// ==================== W transposes -> fp16 ====================
__global__ void conv_wT_kernel(const float* __restrict__ Wq, const float* __restrict__ Wk,
                               const float* __restrict__ Wv, const float* __restrict__ Wo,
                               const float* __restrict__ W1)
{
    __shared__ float t[32][33];
    int z = blockIdx.z;
    if (z == 4) {
        if (blockIdx.x >= 4) return;
        int n0 = blockIdx.x * 32, k0 = blockIdx.y * 32;   // n = p, k = d
        t[threadIdx.y][threadIdx.x] = W1[(size_t)(k0 + threadIdx.y) * PD + n0 + threadIdx.x];
        __syncthreads();
        float v = t[threadIdx.x][threadIdx.y];
        size_t o = (size_t)(n0 + threadIdx.y) * HID + k0 + threadIdx.x;
        __half h = __float2half(v);
        g_w1h[o] = h;
        g_w1l[o] = __float2half(v - __half2float(h));
        return;
    }
    const float* W = (z == 0) ? Wq : (z == 1) ? Wk : (z == 2) ? Wv : Wo;
    int n0 = blockIdx.x * 32, k0 = blockIdx.y * 32;
    t[threadIdx.y][threadIdx.x] = W[(size_t)(k0 + threadIdx.y) * HID + n0 + threadIdx.x];
    __syncthreads();
    float v = t[threadIdx.x][threadIdx.y];
    size_t o = ((size_t)z << 20) + (size_t)(n0 + threadIdx.y) * HID + k0 + threadIdx.x;
    g_wt[o] = __float2half(v);
}

// ==================== repo stage-1 GEMM: fp16 3-pass, pipelined ====================
#define RT       18432                 // 128 rows * 144 B
#define RG_BUF   (4 * RT)
#define RG_SMEM  (2 * RG_BUF)

__global__ __launch_bounds__(256) void repo_gemm_kernel()
{
    extern __shared__ __align__(128) char smem[];
    uint32_t sbase = smem_u32(smem);
    int tid = threadIdx.x, lane = tid & 31, wid = tid >> 5;
    int wm = wid & 3, wn = wid >> 2;

    int ks0 = blockIdx.x * 256;
    int m0  = blockIdx.y * 128;
    const __half* Ah = g_xh  + (size_t)m0 * HID + ks0;
    const __half* Al = g_xl  + (size_t)m0 * HID + ks0;
    const __half* Bh = g_w1h + ks0;
    const __half* Bl = g_w1l + ks0;
    const __half* bases[4] = {Ah, Al, Bh, Bl};

    float acc[2][8][4];
    #pragma unroll
    for (int i = 0; i < 2; i++)
        #pragma unroll
        for (int j = 0; j < 8; j++)
            #pragma unroll
            for (int q = 0; q < 4; q++) acc[i][j][q] = 0.f;

    int arow = lane & 15,  acg = lane >> 4;
    int brow = (lane & 7) + ((lane >> 4) << 3);
    int bcg  = (lane >> 3) & 1;

    #pragma unroll
    for (int it = 0; it < 16; it++) {
        int lin = it * 256 + tid;
        int tile = lin >> 10, idx = lin & 1023, r = idx >> 3, seg = idx & 7;
        cp_async16(sbase + tile * RT + r * 144 + seg * 16,
                   bases[tile] + (size_t)r * HID + seg * 8);
    }
    cp_commit();

    for (int c = 0; c < 4; c++) {
        if (c + 1 < 4) {
            int k0 = (c + 1) * 64;
            uint32_t sb = sbase + ((c + 1) & 1) * RG_BUF;
            #pragma unroll
            for (int it = 0; it < 16; it++) {
                int lin = it * 256 + tid;
                int tile = lin >> 10, idx = lin & 1023, r = idx >> 3, seg = idx & 7;
                cp_async16(sb + tile * RT + r * 144 + seg * 16,
                           bases[tile] + (size_t)r * HID + k0 + seg * 8);
            }
            cp_commit();
            asm volatile("cp.async.wait_group 1;" ::: "memory");
        } else {
            asm volatile("cp.async.wait_group 0;" ::: "memory");
        }
        __syncthreads();

        uint32_t sb = sbase + (c & 1) * RG_BUF;
        uint32_t sAh = sb, sAl = sb + RT, sBh = sb + 2 * RT, sBl = sb + 3 * RT;
        #pragma unroll
        for (int ks = 0; ks < 4; ks++) {
            uint32_t ah[2][4], al[2][4], bh[4][4], bl[4][4];
            #pragma unroll
            for (int i = 0; i < 2; i++) {
                ldsm_x4(ah[i], sAh + ((wm * 32 + i * 16 + arow) * 72 + ks * 16 + acg * 8) * 2);
                ldsm_x4(al[i], sAl + ((wm * 32 + i * 16 + arow) * 72 + ks * 16 + acg * 8) * 2);
            }
            #pragma unroll
            for (int j = 0; j < 4; j++) {
                ldsm_x4(bh[j], sBh + ((wn * 64 + j * 16 + brow) * 72 + ks * 16 + bcg * 8) * 2);
                ldsm_x4(bl[j], sBl + ((wn * 64 + j * 16 + brow) * 72 + ks * 16 + bcg * 8) * 2);
            }
            #pragma unroll
            for (int i = 0; i < 2; i++)
                #pragma unroll
                for (int j = 0; j < 8; j++) {
                    mma16816(acc[i][j], ah[i], bh[j >> 1][(j & 1) * 2], bh[j >> 1][(j & 1) * 2 + 1]);
                    mma16816(acc[i][j], ah[i], bl[j >> 1][(j & 1) * 2], bl[j >> 1][(j & 1) * 2 + 1]);
                    mma16816(acc[i][j], al[i], bh[j >> 1][(j & 1) * 2], bh[j >> 1][(j & 1) * 2 + 1]);
                }
        }
        __syncthreads();
    }

    float* Hs = g_H + (size_t)blockIdx.x * (BB * SS * PD);
    #pragma unroll
    for (int i = 0; i < 2; i++)
        #pragma unroll
        for (int j = 0; j < 8; j++) {
            int n = wn * 64 + j * 8 + (lane & 3) * 2;
            #pragma unroll
            for (int hf = 0; hf < 2; hf++) {
                int m = m0 + wm * 32 + i * 16 + (lane >> 2) + hf * 8;
                *(float2*)(Hs + (size_t)m * PD + n) =
                    make_float2(acc[i][j][hf * 2], acc[i][j][hf * 2 + 1]);
            }
        }
}

// ==================== repo finish ====================
__global__ __launch_bounds__(128) void repo_finish_kernel(
    const float* __restrict__ b1, const float* __restrict__ W2, const float* __restrict__ b2)
{
    int warp = threadIdx.x >> 5, lane = threadIdx.x & 31;
    int r = blockIdx.x * 4 + warp;
    float4 hv = make_float4(0.f, 0.f, 0.f, 0.f);
    #pragma unroll
    for (int sl = 0; sl < 4; sl++) {
        float4 t = *(const float4*)&g_H[(size_t)sl * (BB * SS * PD) + (size_t)r * PD + lane * 4];
        hv.x += t.x; hv.y += t.y; hv.z += t.z; hv.w += t.w;
    }
    float4 bb = *(const float4*)&b1[lane * 4];
    float4 w2 = *(const float4*)&W2[lane * 4];
    float vv[4] = {hv.x + bb.x, hv.y + bb.y, hv.z + bb.z, hv.w + bb.w};
    float ww[4] = {w2.x, w2.y, w2.z, w2.w};
    float sum = 0.f;
    #pragma unroll
    for (int q = 0; q < 4; q++) {
        float z = vv[q];
        float g = 0.5f * z * (1.f + tanhf(0.7978845608028654f * (z + 0.044715f * z * z * z)));
        sum += g * ww[q];
    }
    #pragma unroll
    for (int off = 16; off; off >>= 1) sum += __shfl_xor_sync(0xffffffffu, sum, off);
    if (lane == 0) {
        float raw = sum + b2[0];
        g_sp[r] = fmaxf(raw, 0.f) + log1pf(expf(-fabsf(raw)));
    }
}

// ==================== fp64 scan ====================
__global__ __launch_bounds__(1024) void scan_kernel()
{
    __shared__ double sc[1024];
    int b = blockIdx.x, t = threadIdx.x;
    float a0 = g_sp[b * SS + 2 * t];
    float a1 = g_sp[b * SS + 2 * t + 1];
    sc[t] = (double)a0 + (double)a1;
    __syncthreads();
    for (int off = 1; off < 1024; off <<= 1) {
        double v = (t >= off) ? sc[t - off] : 0.0;
        __syncthreads();
        sc[t] += v;
        __syncthreads();
    }
    double excl = (t == 0) ? 0.0 : sc[t - 1];
    g_posd[b * SS + 2 * t]     = excl + (double)a0;
    g_posd[b * SS + 2 * t + 1] = excl + (double)a0 + (double)a1;
}

// ==================== angles ====================
__global__ __launch_bounds__(256) void angles_kernel()
{
    int idx = blockIdx.x * 256 + threadIdx.x;
    int j = idx & 31, bs = idx >> 5;
    double f   = exp(((double)(-2 * j) / 64.0) * 9.210340371976184);
    double ang = g_posd[bs] * f;
    const double twopi = 6.283185307179586476925286766559;
    ang -= floor(ang * (1.0 / twopi)) * twopi;
    float af = (float)ang;
    g_cos[idx] = cosf(af);
    g_sin[idx] = sinf(af);
}

// ==================== mma.sync fp16 GEMM: 128x128 tile, BK=64, 256 threads ==========
// MODE 0: A = g_xh, B = wt[z], z = 0..2; fused epilogue:
//          z=0/1 -> RoPE -> g_q / g_k (Q scaled 0.125*log2e for exp2 softmax)
//          z=2   -> transpose -> g_vt (b,h,d,s)
// MODE 1: A = g_ah, B = wt[3]; row-major fp32 -> outp
#define TILE_B   18432
#define BUF_B    (2 * TILE_B)
#define SMEM_MM  (2 * BUF_B)

template<int MODE>
__global__ __launch_bounds__(256) void mm_mma_kernel(float* __restrict__ outp)
{
    extern __shared__ __align__(128) char smem[];
    uint32_t sbase = smem_u32(smem);
    int tid = threadIdx.x;
    int lane = tid & 31, wid = tid >> 5;
    int wm = wid & 3, wn = wid >> 2;

    int n0 = blockIdx.x * 128, m0 = blockIdx.y * 128;
    int z  = (MODE == 0) ? (int)blockIdx.z : 3;
    const __half* A = ((MODE == 0) ? g_xh : g_ah) + (size_t)m0 * HID;
    const __half* B = g_wt + ((size_t)z << 20) + (size_t)n0 * HID;

    float acc[2][8][4];
    #pragma unroll
    for (int i = 0; i < 2; i++)
        #pragma unroll
        for (int j = 0; j < 8; j++)
            #pragma unroll
            for (int q = 0; q < 4; q++) acc[i][j][q] = 0.f;

    int arow = lane & 15,  acg = lane >> 4;
    int brow = (lane & 7) + ((lane >> 4) << 3);
    int bcg  = (lane >> 3) & 1;

    {
        const __half* bases[2] = {A, B};
        #pragma unroll
        for (int it = 0; it < 8; it++) {
            int lin = it * 256 + tid;
            int tile = lin >> 10, idx = lin & 1023, r = idx >> 3, seg = idx & 7;
            cp_async16(sbase + tile * TILE_B + r * 144 + seg * 16,
                       bases[tile] + (size_t)r * HID + seg * 8);
        }
        cp_commit();
    }

    for (int c = 0; c < 16; c++) {
        if (c + 1 < 16) {
            int k0 = (c + 1) * 64;
            uint32_t sb = sbase + ((c + 1) & 1) * BUF_B;
            const __half* bases[2] = {A, B};
            #pragma unroll
            for (int it = 0; it < 8; it++) {
                int lin = it * 256 + tid;
                int tile = lin >> 10, idx = lin & 1023, r = idx >> 3, seg = idx & 7;
                cp_async16(sb + tile * TILE_B + r * 144 + seg * 16,
                           bases[tile] + (size_t)r * HID + k0 + seg * 8);
            }
            cp_commit();
            asm volatile("cp.async.wait_group 1;" ::: "memory");
        } else {
            asm volatile("cp.async.wait_group 0;" ::: "memory");
        }
        __syncthreads();

        uint32_t sb = sbase + (c & 1) * BUF_B;
        uint32_t sA = sb, sB = sb + TILE_B;

        #pragma unroll
        for (int ks = 0; ks < 4; ks++) {
            uint32_t a[2][4], bh[4][4];
            #pragma unroll
            for (int i = 0; i < 2; i++)
                ldsm_x4(a[i], sA + ((wm * 32 + i * 16 + arow) * 72 + ks * 16 + acg * 8) * 2);
            #pragma unroll
            for (int j = 0; j < 4; j++)
                ldsm_x4(bh[j], sB + ((wn * 64 + j * 16 + brow) * 72 + ks * 16 + bcg * 8) * 2);
            #pragma unroll
            for (int i = 0; i < 2; i++)
                #pragma unroll
                for (int j = 0; j < 8; j++)
                    mma16816(acc[i][j], a[i], bh[j >> 1][(j & 1) * 2], bh[j >> 1][(j & 1) * 2 + 1]);
        }
        __syncthreads();
    }

    // ---- epilogue ----
    if (MODE == 1) {
        #pragma unroll
        for (int i = 0; i < 2; i++)
            #pragma unroll
            for (int j = 0; j < 8; j++) {
                int n = n0 + wn * 64 + j * 8 + (lane & 3) * 2;
                #pragma unroll
                for (int hf = 0; hf < 2; hf++) {
                    int m = m0 + wm * 32 + i * 16 + (lane >> 2) + hf * 8;
                    *(float2*)(outp + (size_t)m * HID + n) =
                        make_float2(acc[i][j][hf * 2], acc[i][j][hf * 2 + 1]);
                }
            }
        return;
    }

    int h = (n0 + wn * 64) >> 6;
    if (z == 2) {
        #pragma unroll
        for (int i = 0; i < 2; i++)
            #pragma unroll
            for (int hf = 0; hf < 2; hf++) {
                int m = m0 + wm * 32 + i * 16 + (lane >> 2) + hf * 8;
                int b = m >> 11, s = m & 2047;
                size_t basev = ((size_t)(b * HH + h)) * DD * SS + s;
                #pragma unroll
                for (int j = 0; j < 8; j++) {
                    int d = j * 8 + (lane & 3) * 2;
                    g_vt[basev + (size_t)d * SS]       = __float2half(acc[i][j][hf * 2]);
                    g_vt[basev + (size_t)(d + 1) * SS] = __float2half(acc[i][j][hf * 2 + 1]);
                }
            }
    } else {
        __half* dst = (z == 0) ? g_q : g_k;
        // Q scale folds 1/sqrt(64) * log2(e) so flash softmax works in exp2 domain
        float qscale = (z == 0) ? 0.18033688011112042f : 1.0f;
        #pragma unroll
        for (int i = 0; i < 2; i++)
            #pragma unroll
            for (int hf = 0; hf < 2; hf++) {
                int m = m0 + wm * 32 + i * 16 + (lane >> 2) + hf * 8;
                int b = m >> 11, s = m & 2047;
                size_t baseo = ((size_t)((b * HH + h) * SS + s)) * DD;
                int cbase = (b * SS + s) * 32;
                #pragma unroll
                for (int j = 0; j < 4; j++) {
                    int d = j * 8 + (lane & 3) * 2;
                    float c0 = g_cos[cbase + d],     sn0 = g_sin[cbase + d];
                    float c1 = g_cos[cbase + d + 1], sn1 = g_sin[cbase + d + 1];
                    float t1a = acc[i][j][hf * 2],     t1b = acc[i][j][hf * 2 + 1];
                    float t2a = acc[i][j + 4][hf * 2], t2b = acc[i][j + 4][hf * 2 + 1];
                    float ra  = qscale * (t1a * c0 - t2a * sn0);
                    float rb  = qscale * (t1b * c1 - t2b * sn1);
                    float r2a = qscale * (t1a * sn0 + t2a * c0);
                    float r2b = qscale * (t1b * sn1 + t2b * c1);
                    *(uint32_t*)&dst[baseo + d]      = pack_h(ra, rb);
                    *(uint32_t*)&dst[baseo + d + 32] = pack_h(r2a, r2b);
                }
            }
    }
}

// ==================== Flash attention: BQ=128, BKV=64, exp2-poly softmax ====================
#define FT     9216
#define FBUF   (2 * FT)
#define SMEM_F (2 * FBUF)

__global__ __launch_bounds__(256, 2) void flash_mma_kernel()
{
    extern __shared__ __align__(128) char fsm[];
    uint32_t sbase = smem_u32(fsm);
    int tid = threadIdx.x, lane = tid & 31, w = tid >> 5;
    int qt = blockIdx.x, bh = blockIdx.y;
    int b = bh >> 4, h = bh & 15;

    const __half* Q  = g_q  + ((size_t)bh * SS + qt * 128) * DD;
    const __half* K  = g_k  + (size_t)bh * SS * DD;
    const __half* Vt = g_vt + (size_t)bh * DD * SS;

    int arow = lane & 15, acg = lane >> 4;
    int brow = (lane & 7) + ((lane >> 4) << 3), bcg = (lane >> 3) & 1;

    #pragma unroll
    for (int it = 0; it < 4; it++) {
        int lin = it * 256 + tid;
        int r = lin >> 3, seg = lin & 7;
        cp_async16(sbase + r * 144 + seg * 16, Q + (size_t)r * DD + seg * 8);
    }
    cp_commit();
    asm volatile("cp.async.wait_group 0;" ::: "memory");
    __syncthreads();
    uint32_t aq[4][4];
    #pragma unroll
    for (int kb = 0; kb < 4; kb++)
        ldsm_x4(aq[kb], sbase + ((w * 16 + arow) * 72 + kb * 16 + acg * 8) * 2);
    __syncthreads();

    float s[8][4], o[8][4];
    #pragma unroll
    for (int j = 0; j < 8; j++)
        #pragma unroll
        for (int q = 0; q < 4; q++) o[j][q] = 0.f;
    float m0 = -1e30f, m1 = -1e30f, l0 = 0.f, l1 = 0.f;

    {
        #pragma unroll
        for (int it = 0; it < 4; it++) {
            int lin = it * 256 + tid;
            int tile = lin >> 9, idx = lin & 511;
            int r = idx >> 3, seg = idx & 7;
            const __half* src = (tile == 0) ? K  + (size_t)r * DD + seg * 8
                                            : Vt + (size_t)r * SS + seg * 8;
            cp_async16(sbase + tile * FT + r * 144 + seg * 16, src);
        }
        cp_commit();
    }

    for (int c = 0; c < 32; c++) {
        if (c + 1 < 32) {
            int kbase = (c + 1) * 64;
            uint32_t sb = sbase + ((c + 1) & 1) * FBUF;
            #pragma unroll
            for (int it = 0; it < 4; it++) {
                int lin = it * 256 + tid;
                int tile = lin >> 9, idx = lin & 511;
                int r = idx >> 3, seg = idx & 7;
                const __half* src = (tile == 0) ? K  + (size_t)(kbase + r) * DD + seg * 8
                                                : Vt + (size_t)r * SS + kbase + seg * 8;
                cp_async16(sb + tile * FT + r * 144 + seg * 16, src);
            }
            cp_commit();
            asm volatile("cp.async.wait_group 1;" ::: "memory");
        } else {
            asm volatile("cp.async.wait_group 0;" ::: "memory");
        }
        __syncthreads();

        uint32_t sb = sbase + (c & 1) * FBUF;

        #pragma unroll
        for (int j = 0; j < 8; j++) { s[j][0] = s[j][1] = s[j][2] = s[j][3] = 0.f; }
        #pragma unroll
        for (int kb = 0; kb < 4; kb++) {
            uint32_t kh[4][4];
            #pragma unroll
            for (int j = 0; j < 4; j++)
                ldsm_x4(kh[j], sb + ((j * 16 + brow) * 72 + kb * 16 + bcg * 8) * 2);
            #pragma unroll
            for (int j = 0; j < 8; j++)
                mma16816(s[j], aq[kb], kh[j >> 1][(j & 1) * 2], kh[j >> 1][(j & 1) * 2 + 1]);
        }

        // ---- online softmax, log2 domain, poly exp2 (no MUFU) ----
        float mx0 = s[0][0], mx1 = s[0][2];
        #pragma unroll
        for (int j = 0; j < 8; j++) {
            mx0 = fmaxf(mx0, fmaxf(s[j][0], s[j][1]));
            mx1 = fmaxf(mx1, fmaxf(s[j][2], s[j][3]));
        }
        mx0 = fmaxf(mx0, __shfl_xor_sync(0xffffffffu, mx0, 1));
        mx0 = fmaxf(mx0, __shfl_xor_sync(0xffffffffu, mx0, 2));
        mx1 = fmaxf(mx1, __shfl_xor_sync(0xffffffffu, mx1, 1));
        mx1 = fmaxf(mx1, __shfl_xor_sync(0xffffffffu, mx1, 2));
        float mn0 = fmaxf(m0, mx0), mn1 = fmaxf(m1, mx1);
        float al0 = fexp2(m0 - mn0), al1 = fexp2(m1 - mn1);
        m0 = mn0; m1 = mn1;
        float sum0 = 0.f, sum1 = 0.f;
        #pragma unroll
        for (int j = 0; j < 8; j++) {
            s[j][0] = fexp2(s[j][0] - mn0);
            s[j][1] = fexp2(s[j][1] - mn0);
            s[j][2] = fexp2(s[j][2] - mn1);
            s[j][3] = fexp2(s[j][3] - mn1);
            sum0 += s[j][0] + s[j][1];
            sum1 += s[j][2] + s[j][3];
        }
        sum0 += __shfl_xor_sync(0xffffffffu, sum0, 1);
        sum0 += __shfl_xor_sync(0xffffffffu, sum0, 2);
        sum1 += __shfl_xor_sync(0xffffffffu, sum1, 1);
        sum1 += __shfl_xor_sync(0xffffffffu, sum1, 2);
        l0 = l0 * al0 + sum0;
        l1 = l1 * al1 + sum1;
        #pragma unroll
        for (int j = 0; j < 8; j++) {
            o[j][0] *= al0; o[j][1] *= al0; o[j][2] *= al1; o[j][3] *= al1;
        }

        #pragma unroll
        for (int kb = 0; kb < 4; kb++) {
            uint32_t ph[4];
            ph[0] = pack_h(s[2 * kb][0],     s[2 * kb][1]);
            ph[1] = pack_h(s[2 * kb][2],     s[2 * kb][3]);
            ph[2] = pack_h(s[2 * kb + 1][0], s[2 * kb + 1][1]);
            ph[3] = pack_h(s[2 * kb + 1][2], s[2 * kb + 1][3]);

            uint32_t vh[4][4];
            #pragma unroll
            for (int j = 0; j < 4; j++)
                ldsm_x4(vh[j], sb + FT + ((j * 16 + brow) * 72 + kb * 16 + bcg * 8) * 2);
            #pragma unroll
            for (int j = 0; j < 8; j++)
                mma16816(o[j], ph, vh[j >> 1][(j & 1) * 2], vh[j >> 1][(j & 1) * 2 + 1]);
        }
        __syncthreads();
    }

    float i0 = 1.f / l0, i1 = 1.f / l1;
    int r0 = qt * 128 + w * 16 + (lane >> 2);
    #pragma unroll
    for (int j = 0; j < 8; j++) {
        int n = h * 64 + j * 8 + (lane & 3) * 2;
        size_t o0 = ((size_t)(b * SS) + r0) * HID + n;
        size_t o1 = o0 + 8 * HID;
        *(uint32_t*)&g_ah[o0] = pack_h(o[j][0] * i0, o[j][1] * i0);
        *(uint32_t*)&g_ah[o1] = pack_h(o[j][2] * i1, o[j][3] * i1);
    }
}

// ==================== launch (serial) ====================
extern "C" void kernel_launch(void* const* d_in, const int* in_sizes, int n_in,
                              void* d_out, int out_size)
{
    const float* x  = (const float*)d_in[0];
    const float* Wq = (const float*)d_in[1];
    const float* Wk = (const float*)d_in[2];
    const float* Wv = (const float*)d_in[3];
    const float* Wo = (const float*)d_in[4];
    const float* W1 = (const float*)d_in[5];
    const float* b1 = (const float*)d_in[6];
    const float* W2 = (const float*)d_in[7];
    const float* b2 = (const float*)d_in[8];
    float* out = (float*)d_out;

    cudaFuncSetAttribute(mm_mma_kernel<0>, cudaFuncAttributeMaxDynamicSharedMemorySize, SMEM_MM);
    cudaFuncSetAttribute(mm_mma_kernel<1>, cudaFuncAttributeMaxDynamicSharedMemorySize, SMEM_MM);
    cudaFuncSetAttribute(flash_mma_kernel, cudaFuncAttributeMaxDynamicSharedMemorySize, SMEM_F);
    cudaFuncSetAttribute(repo_gemm_kernel, cudaFuncAttributeMaxDynamicSharedMemorySize, RG_SMEM);

    conv_x_kernel<<<4096, 256>>>(x);
    conv_wT_kernel<<<dim3(32, 32, 5), dim3(32, 32)>>>(Wq, Wk, Wv, Wo, W1);
    repo_gemm_kernel<<<dim3(4, 32), 256, RG_SMEM>>>();
    repo_finish_kernel<<<1024, 128>>>(b1, W2, b2);
    scan_kernel<<<2, 1024>>>();
    angles_kernel<<<512, 256>>>();
    mm_mma_kernel<0><<<dim3(8, 32, 3), 256, SMEM_MM>>>(nullptr);
    flash_mma_kernel<<<dim3(16, 32), 256, SMEM_F>>>();
    mm_mma_kernel<1><<<dim3(8, 32), 256, SMEM_MM>>>(out);
}

// round 14
// speedup vs baseline: 1.1251x; 1.1251x over previous
#include <cuda_runtime.h>
#include <cuda_fp16.h>
#include <math.h>
#include <stdint.h>

#define BB   2
#define SS   2048
#define HH   16
#define DD   64
#define HID  1024
#define PD   128

// ---------------- scratch (device globals — no allocation allowed) ----------------
__device__ float  g_sp[BB*SS];
__device__ double g_posd[BB*SS];
__device__ __align__(256) float g_cos[BB*SS*32];
__device__ __align__(256) float g_sin[BB*SS*32];
// fp16 operands
__device__ __align__(256) __half g_xh[BB*SS*HID];        // x fp16 (hi)
__device__ __align__(256) __half g_xl[BB*SS*HID];        // x fp16 (lo residual)
__device__ __align__(256) __half g_ah[BB*SS*HID];        // attention out fp16
__device__ __align__(256) __half g_wt[4*HID*HID];        // W^T (n,k) fp16, z = q,k,v,o
__device__ __align__(256) __half g_w1h[PD*HID];          // W1^T (p,d) fp16 hi
__device__ __align__(256) __half g_w1l[PD*HID];          // W1^T (p,d) fp16 lo
__device__ __align__(256) float  g_H[4*BB*SS*PD];        // repo H partials, 4 k-slices
__device__ __align__(256) __half g_q[BB*HH*SS*DD];       // (b,h,s,d), RoPE'd, scaled 0.125*log2e
__device__ __align__(256) __half g_k[BB*HH*SS*DD];       // (b,h,s,d), RoPE'd
__device__ __align__(256) __half g_vt[BB*HH*DD*SS];      // (b,h,d,s)  V^T

// ==================== helpers ====================
__device__ __forceinline__ uint32_t smem_u32(const void* p) {
    uint32_t a;
    asm("{ .reg .u64 t; cvta.to.shared.u64 t, %1; cvt.u32.u64 %0, t; }" : "=r"(a) : "l"(p));
    return a;
}
__device__ __forceinline__ void cp_async16(uint32_t dst, const void* src) {
    asm volatile("cp.async.cg.shared.global [%0], [%1], 16;" :: "r"(dst), "l"(src));
}
__device__ __forceinline__ void cp_commit() {
    asm volatile("cp.async.commit_group;" ::: "memory");
}
__device__ __forceinline__ void ldsm_x4(uint32_t* r, uint32_t addr) {
    asm volatile("ldmatrix.sync.aligned.m8n8.x4.shared.b16 {%0,%1,%2,%3}, [%4];"
                 : "=r"(r[0]), "=r"(r[1]), "=r"(r[2]), "=r"(r[3]) : "r"(addr));
}
__device__ __forceinline__ void mma16816(float* c, const uint32_t* a, uint32_t b0, uint32_t b1) {
    asm volatile(
        "mma.sync.aligned.m16n8k16.row.col.f32.f16.f16.f32 "
        "{%0,%1,%2,%3}, {%4,%5,%6,%7}, {%8,%9}, {%0,%1,%2,%3};"
        : "+f"(c[0]), "+f"(c[1]), "+f"(c[2]), "+f"(c[3])
        : "r"(a[0]), "r"(a[1]), "r"(a[2]), "r"(a[3]), "r"(b0), "r"(b1));
}
// pack two fp32 -> f16x2 (first arg -> low half)
__device__ __forceinline__ uint32_t pack_h(float lo, float hi) {
    uint32_t r;
    asm("cvt.rn.f16x2.f32 %0, %2, %1;" : "=r"(r) : "f"(lo), "f"(hi));
    return r;
}
// hardware exp2: single EX2 via MUFU (no log2e multiply)
__device__ __forceinline__ float hexp2(float x) {
    float r;
    asm("ex2.approx.f32 %0, %1;" : "=f"(r) : "f"(x));
    return r;
}

// ==================== fp32 x -> fp16 hi/lo ====================
__global__ __launch_bounds__(256) void conv_x_kernel(const float* __restrict__ src)
{
    int idx = (blockIdx.x * 256 + threadIdx.x) * 4;
    float4 v = *(const float4*)&src[idx];
    __half hx = __float2half(v.x), hy = __float2half(v.y);
    __half hz = __float2half(v.z), hw = __float2half(v.w);
    uint2 H, L;
    H.x = pack_h(v.x, v.y);
    H.y = pack_h(v.z, v.w);
    L.x = pack_h(v.x - __half2float(hx), v.y - __half2float(hy));
    L.y = pack_h(v.z - __half2float(hz), v.w - __half2float(hw));
    *(uint2*)&g_xh[idx] = H;
    *(uint2*)&g_xl[idx] = L;
}

// ==================== W transposes -> fp16 ====================
__global__ void conv_wT_kernel(const float* __restrict__ Wq, const float* __restrict__ Wk,
                               const float* __restrict__ Wv, const float* __restrict__ Wo,
                               const float* __restrict__ W1)
{
    __shared__ float t[32][33];
    int z = blockIdx.z;
    if (z == 4) {
        if (blockIdx.x >= 4) return;
        int n0 = blockIdx.x * 32, k0 = blockIdx.y * 32;   // n = p, k = d
        t[threadIdx.y][threadIdx.x] = W1[(size_t)(k0 + threadIdx.y) * PD + n0 + threadIdx.x];
        __syncthreads();
        float v = t[threadIdx.x][threadIdx.y];
        size_t o = (size_t)(n0 + threadIdx.y) * HID + k0 + threadIdx.x;
        __half h = __float2half(v);
        g_w1h[o] = h;
        g_w1l[o] = __float2half(v - __half2float(h));
        return;
    }
    const float* W = (z == 0) ? Wq : (z == 1) ? Wk : (z == 2) ? Wv : Wo;
    int n0 = blockIdx.x * 32, k0 = blockIdx.y * 32;
    t[threadIdx.y][threadIdx.x] = W[(size_t)(k0 + threadIdx.y) * HID + n0 + threadIdx.x];
    __syncthreads();
    float v = t[threadIdx.x][threadIdx.y];
    size_t o = ((size_t)z << 20) + (size_t)(n0 + threadIdx.y) * HID + k0 + threadIdx.x;
    g_wt[o] = __float2half(v);
}

// ==================== repo stage-1 GEMM: fp16 3-pass, pipelined ====================
#define RT       18432                 // 128 rows * 144 B
#define RG_BUF   (4 * RT)
#define RG_SMEM  (2 * RG_BUF)

__global__ __launch_bounds__(256) void repo_gemm_kernel()
{
    extern __shared__ __align__(128) char smem[];
    uint32_t sbase = smem_u32(smem);
    int tid = threadIdx.x, lane = tid & 31, wid = tid >> 5;
    int wm = wid & 3, wn = wid >> 2;

    int ks0 = blockIdx.x * 256;
    int m0  = blockIdx.y * 128;
    const __half* Ah = g_xh  + (size_t)m0 * HID + ks0;
    const __half* Al = g_xl  + (size_t)m0 * HID + ks0;
    const __half* Bh = g_w1h + ks0;
    const __half* Bl = g_w1l + ks0;
    const __half* bases[4] = {Ah, Al, Bh, Bl};

    float acc[2][8][4];
    #pragma unroll
    for (int i = 0; i < 2; i++)
        #pragma unroll
        for (int j = 0; j < 8; j++)
            #pragma unroll
            for (int q = 0; q < 4; q++) acc[i][j][q] = 0.f;

    int arow = lane & 15,  acg = lane >> 4;
    int brow = (lane & 7) + ((lane >> 4) << 3);
    int bcg  = (lane >> 3) & 1;

    #pragma unroll
    for (int it = 0; it < 16; it++) {
        int lin = it * 256 + tid;
        int tile = lin >> 10, idx = lin & 1023, r = idx >> 3, seg = idx & 7;
        cp_async16(sbase + tile * RT + r * 144 + seg * 16,
                   bases[tile] + (size_t)r * HID + seg * 8);
    }
    cp_commit();

    for (int c = 0; c < 4; c++) {
        if (c + 1 < 4) {
            int k0 = (c + 1) * 64;
            uint32_t sb = sbase + ((c + 1) & 1) * RG_BUF;
            #pragma unroll
            for (int it = 0; it < 16; it++) {
                int lin = it * 256 + tid;
                int tile = lin >> 10, idx = lin & 1023, r = idx >> 3, seg = idx & 7;
                cp_async16(sb + tile * RT + r * 144 + seg * 16,
                           bases[tile] + (size_t)r * HID + k0 + seg * 8);
            }
            cp_commit();
            asm volatile("cp.async.wait_group 1;" ::: "memory");
        } else {
            asm volatile("cp.async.wait_group 0;" ::: "memory");
        }
        __syncthreads();

        uint32_t sb = sbase + (c & 1) * RG_BUF;
        uint32_t sAh = sb, sAl = sb + RT, sBh = sb + 2 * RT, sBl = sb + 3 * RT;
        #pragma unroll
        for (int ks = 0; ks < 4; ks++) {
            uint32_t ah[2][4], al[2][4], bh[4][4], bl[4][4];
            #pragma unroll
            for (int i = 0; i < 2; i++) {
                ldsm_x4(ah[i], sAh + ((wm * 32 + i * 16 + arow) * 72 + ks * 16 + acg * 8) * 2);
                ldsm_x4(al[i], sAl + ((wm * 32 + i * 16 + arow) * 72 + ks * 16 + acg * 8) * 2);
            }
            #pragma unroll
            for (int j = 0; j < 4; j++) {
                ldsm_x4(bh[j], sBh + ((wn * 64 + j * 16 + brow) * 72 + ks * 16 + bcg * 8) * 2);
                ldsm_x4(bl[j], sBl + ((wn * 64 + j * 16 + brow) * 72 + ks * 16 + bcg * 8) * 2);
            }
            #pragma unroll
            for (int i = 0; i < 2; i++)
                #pragma unroll
                for (int j = 0; j < 8; j++) {
                    mma16816(acc[i][j], ah[i], bh[j >> 1][(j & 1) * 2], bh[j >> 1][(j & 1) * 2 + 1]);
                    mma16816(acc[i][j], ah[i], bl[j >> 1][(j & 1) * 2], bl[j >> 1][(j & 1) * 2 + 1]);
                    mma16816(acc[i][j], al[i], bh[j >> 1][(j & 1) * 2], bh[j >> 1][(j & 1) * 2 + 1]);
                }
        }
        __syncthreads();
    }

    float* Hs = g_H + (size_t)blockIdx.x * (BB * SS * PD);
    #pragma unroll
    for (int i = 0; i < 2; i++)
        #pragma unroll
        for (int j = 0; j < 8; j++) {
            int n = wn * 64 + j * 8 + (lane & 3) * 2;
            #pragma unroll
            for (int hf = 0; hf < 2; hf++) {
                int m = m0 + wm * 32 + i * 16 + (lane >> 2) + hf * 8;
                *(float2*)(Hs + (size_t)m * PD + n) =
                    make_float2(acc[i][j][hf * 2], acc[i][j][hf * 2 + 1]);
            }
        }
}

// ==================== repo finish ====================
__global__ __launch_bounds__(128) void repo_finish_kernel(
    const float* __restrict__ b1, const float* __restrict__ W2, const float* __restrict__ b2)
{
    int warp = threadIdx.x >> 5, lane = threadIdx.x & 31;
    int r = blockIdx.x * 4 + warp;
    float4 hv = make_float4(0.f, 0.f, 0.f, 0.f);
    #pragma unroll
    for (int sl = 0; sl < 4; sl++) {
        float4 t = *(const float4*)&g_H[(size_t)sl * (BB * SS * PD) + (size_t)r * PD + lane * 4];
        hv.x += t.x; hv.y += t.y; hv.z += t.z; hv.w += t.w;
    }
    float4 bb = *(const float4*)&b1[lane * 4];
    float4 w2 = *(const float4*)&W2[lane * 4];
    float vv[4] = {hv.x + bb.x, hv.y + bb.y, hv.z + bb.z, hv.w + bb.w};
    float ww[4] = {w2.x, w2.y, w2.z, w2.w};
    float sum = 0.f;
    #pragma unroll
    for (int q = 0; q < 4; q++) {
        float z = vv[q];
        float g = 0.5f * z * (1.f + tanhf(0.7978845608028654f * (z + 0.044715f * z * z * z)));
        sum += g * ww[q];
    }
    #pragma unroll
    for (int off = 16; off; off >>= 1) sum += __shfl_xor_sync(0xffffffffu, sum, off);
    if (lane == 0) {
        float raw = sum + b2[0];
        g_sp[r] = fmaxf(raw, 0.f) + log1pf(expf(-fabsf(raw)));
    }
}

// ==================== fp64 scan ====================
__global__ __launch_bounds__(1024) void scan_kernel()
{
    __shared__ double sc[1024];
    int b = blockIdx.x, t = threadIdx.x;
    float a0 = g_sp[b * SS + 2 * t];
    float a1 = g_sp[b * SS + 2 * t + 1];
    sc[t] = (double)a0 + (double)a1;
    __syncthreads();
    for (int off = 1; off < 1024; off <<= 1) {
        double v = (t >= off) ? sc[t - off] : 0.0;
        __syncthreads();
        sc[t] += v;
        __syncthreads();
    }
    double excl = (t == 0) ? 0.0 : sc[t - 1];
    g_posd[b * SS + 2 * t]     = excl + (double)a0;
    g_posd[b * SS + 2 * t + 1] = excl + (double)a0 + (double)a1;
}

// ==================== angles ====================
__global__ __launch_bounds__(256) void angles_kernel()
{
    int idx = blockIdx.x * 256 + threadIdx.x;
    int j = idx & 31, bs = idx >> 5;
    double f   = exp(((double)(-2 * j) / 64.0) * 9.210340371976184);
    double ang = g_posd[bs] * f;
    const double twopi = 6.283185307179586476925286766559;
    ang -= floor(ang * (1.0 / twopi)) * twopi;
    float af = (float)ang;
    g_cos[idx] = cosf(af);
    g_sin[idx] = sinf(af);
}

// ==================== mma.sync fp16 GEMM: 128x128 tile, BK=64, 256 threads ==========
// MODE 0: A = g_xh, B = wt[z], z = 0..2; fused epilogue:
//          z=0/1 -> RoPE -> g_q / g_k (Q scaled 0.125*log2e for exp2 softmax)
//          z=2   -> transpose -> g_vt (b,h,d,s)
// MODE 1: A = g_ah, B = wt[3]; row-major fp32 -> outp
#define TILE_B   18432
#define BUF_B    (2 * TILE_B)
#define SMEM_MM  (2 * BUF_B)

template<int MODE>
__global__ __launch_bounds__(256) void mm_mma_kernel(float* __restrict__ outp)
{
    extern __shared__ __align__(128) char smem[];
    uint32_t sbase = smem_u32(smem);
    int tid = threadIdx.x;
    int lane = tid & 31, wid = tid >> 5;
    int wm = wid & 3, wn = wid >> 2;

    int n0 = blockIdx.x * 128, m0 = blockIdx.y * 128;
    int z  = (MODE == 0) ? (int)blockIdx.z : 3;
    const __half* A = ((MODE == 0) ? g_xh : g_ah) + (size_t)m0 * HID;
    const __half* B = g_wt + ((size_t)z << 20) + (size_t)n0 * HID;

    float acc[2][8][4];
    #pragma unroll
    for (int i = 0; i < 2; i++)
        #pragma unroll
        for (int j = 0; j < 8; j++)
            #pragma unroll
            for (int q = 0; q < 4; q++) acc[i][j][q] = 0.f;

    int arow = lane & 15,  acg = lane >> 4;
    int brow = (lane & 7) + ((lane >> 4) << 3);
    int bcg  = (lane >> 3) & 1;

    {
        const __half* bases[2] = {A, B};
        #pragma unroll
        for (int it = 0; it < 8; it++) {
            int lin = it * 256 + tid;
            int tile = lin >> 10, idx = lin & 1023, r = idx >> 3, seg = idx & 7;
            cp_async16(sbase + tile * TILE_B + r * 144 + seg * 16,
                       bases[tile] + (size_t)r * HID + seg * 8);
        }
        cp_commit();
    }

    for (int c = 0; c < 16; c++) {
        if (c + 1 < 16) {
            int k0 = (c + 1) * 64;
            uint32_t sb = sbase + ((c + 1) & 1) * BUF_B;
            const __half* bases[2] = {A, B};
            #pragma unroll
            for (int it = 0; it < 8; it++) {
                int lin = it * 256 + tid;
                int tile = lin >> 10, idx = lin & 1023, r = idx >> 3, seg = idx & 7;
                cp_async16(sb + tile * TILE_B + r * 144 + seg * 16,
                           bases[tile] + (size_t)r * HID + k0 + seg * 8);
            }
            cp_commit();
            asm volatile("cp.async.wait_group 1;" ::: "memory");
        } else {
            asm volatile("cp.async.wait_group 0;" ::: "memory");
        }
        __syncthreads();

        uint32_t sb = sbase + (c & 1) * BUF_B;
        uint32_t sA = sb, sB = sb + TILE_B;

        #pragma unroll
        for (int ks = 0; ks < 4; ks++) {
            uint32_t a[2][4], bh[4][4];
            #pragma unroll
            for (int i = 0; i < 2; i++)
                ldsm_x4(a[i], sA + ((wm * 32 + i * 16 + arow) * 72 + ks * 16 + acg * 8) * 2);
            #pragma unroll
            for (int j = 0; j < 4; j++)
                ldsm_x4(bh[j], sB + ((wn * 64 + j * 16 + brow) * 72 + ks * 16 + bcg * 8) * 2);
            #pragma unroll
            for (int i = 0; i < 2; i++)
                #pragma unroll
                for (int j = 0; j < 8; j++)
                    mma16816(acc[i][j], a[i], bh[j >> 1][(j & 1) * 2], bh[j >> 1][(j & 1) * 2 + 1]);
        }
        __syncthreads();
    }

    // ---- epilogue ----
    if (MODE == 1) {
        #pragma unroll
        for (int i = 0; i < 2; i++)
            #pragma unroll
            for (int j = 0; j < 8; j++) {
                int n = n0 + wn * 64 + j * 8 + (lane & 3) * 2;
                #pragma unroll
                for (int hf = 0; hf < 2; hf++) {
                    int m = m0 + wm * 32 + i * 16 + (lane >> 2) + hf * 8;
                    *(float2*)(outp + (size_t)m * HID + n) =
                        make_float2(acc[i][j][hf * 2], acc[i][j][hf * 2 + 1]);
                }
            }
        return;
    }

    int h = (n0 + wn * 64) >> 6;
    if (z == 2) {
        #pragma unroll
        for (int i = 0; i < 2; i++)
            #pragma unroll
            for (int hf = 0; hf < 2; hf++) {
                int m = m0 + wm * 32 + i * 16 + (lane >> 2) + hf * 8;
                int b = m >> 11, s = m & 2047;
                size_t basev = ((size_t)(b * HH + h)) * DD * SS + s;
                #pragma unroll
                for (int j = 0; j < 8; j++) {
                    int d = j * 8 + (lane & 3) * 2;
                    g_vt[basev + (size_t)d * SS]       = __float2half(acc[i][j][hf * 2]);
                    g_vt[basev + (size_t)(d + 1) * SS] = __float2half(acc[i][j][hf * 2 + 1]);
                }
            }
    } else {
        __half* dst = (z == 0) ? g_q : g_k;
        // Q scale folds 1/sqrt(64) * log2(e) so flash softmax works in exp2 domain
        float qscale = (z == 0) ? 0.18033688011112042f : 1.0f;
        #pragma unroll
        for (int i = 0; i < 2; i++)
            #pragma unroll
            for (int hf = 0; hf < 2; hf++) {
                int m = m0 + wm * 32 + i * 16 + (lane >> 2) + hf * 8;
                int b = m >> 11, s = m & 2047;
                size_t baseo = ((size_t)((b * HH + h) * SS + s)) * DD;
                int cbase = (b * SS + s) * 32;
                #pragma unroll
                for (int j = 0; j < 4; j++) {
                    int d = j * 8 + (lane & 3) * 2;
                    float c0 = g_cos[cbase + d],     sn0 = g_sin[cbase + d];
                    float c1 = g_cos[cbase + d + 1], sn1 = g_sin[cbase + d + 1];
                    float t1a = acc[i][j][hf * 2],     t1b = acc[i][j][hf * 2 + 1];
                    float t2a = acc[i][j + 4][hf * 2], t2b = acc[i][j + 4][hf * 2 + 1];
                    float ra  = qscale * (t1a * c0 - t2a * sn0);
                    float rb  = qscale * (t1b * c1 - t2b * sn1);
                    float r2a = qscale * (t1a * sn0 + t2a * c0);
                    float r2b = qscale * (t1b * sn1 + t2b * c1);
                    *(uint32_t*)&dst[baseo + d]      = pack_h(ra, rb);
                    *(uint32_t*)&dst[baseo + d + 32] = pack_h(r2a, r2b);
                }
            }
    }
}

// ==================== Flash attention: BQ=128, BKV=64, exp2 (MUFU) softmax ====================
#define FT     9216
#define FBUF   (2 * FT)
#define SMEM_F (2 * FBUF)

__global__ __launch_bounds__(256, 2) void flash_mma_kernel()
{
    extern __shared__ __align__(128) char fsm[];
    uint32_t sbase = smem_u32(fsm);
    int tid = threadIdx.x, lane = tid & 31, w = tid >> 5;
    int qt = blockIdx.x, bh = blockIdx.y;
    int b = bh >> 4, h = bh & 15;

    const __half* Q  = g_q  + ((size_t)bh * SS + qt * 128) * DD;
    const __half* K  = g_k  + (size_t)bh * SS * DD;
    const __half* Vt = g_vt + (size_t)bh * DD * SS;

    int arow = lane & 15, acg = lane >> 4;
    int brow = (lane & 7) + ((lane >> 4) << 3), bcg = (lane >> 3) & 1;

    #pragma unroll
    for (int it = 0; it < 4; it++) {
        int lin = it * 256 + tid;
        int r = lin >> 3, seg = lin & 7;
        cp_async16(sbase + r * 144 + seg * 16, Q + (size_t)r * DD + seg * 8);
    }
    cp_commit();
    asm volatile("cp.async.wait_group 0;" ::: "memory");
    __syncthreads();
    uint32_t aq[4][4];
    #pragma unroll
    for (int kb = 0; kb < 4; kb++)
        ldsm_x4(aq[kb], sbase + ((w * 16 + arow) * 72 + kb * 16 + acg * 8) * 2);
    __syncthreads();

    float s[8][4], o[8][4];
    #pragma unroll
    for (int j = 0; j < 8; j++)
        #pragma unroll
        for (int q = 0; q < 4; q++) o[j][q] = 0.f;
    float m0 = -1e30f, m1 = -1e30f, l0 = 0.f, l1 = 0.f;

    {
        #pragma unroll
        for (int it = 0; it < 4; it++) {
            int lin = it * 256 + tid;
            int tile = lin >> 9, idx = lin & 511;
            int r = idx >> 3, seg = idx & 7;
            const __half* src = (tile == 0) ? K  + (size_t)r * DD + seg * 8
                                            : Vt + (size_t)r * SS + seg * 8;
            cp_async16(sbase + tile * FT + r * 144 + seg * 16, src);
        }
        cp_commit();
    }

    for (int c = 0; c < 32; c++) {
        if (c + 1 < 32) {
            int kbase = (c + 1) * 64;
            uint32_t sb = sbase + ((c + 1) & 1) * FBUF;
            #pragma unroll
            for (int it = 0; it < 4; it++) {
                int lin = it * 256 + tid;
                int tile = lin >> 9, idx = lin & 511;
                int r = idx >> 3, seg = idx & 7;
                const __half* src = (tile == 0) ? K  + (size_t)(kbase + r) * DD + seg * 8
                                                : Vt + (size_t)r * SS + kbase + seg * 8;
                cp_async16(sb + tile * FT + r * 144 + seg * 16, src);
            }
            cp_commit();
            asm volatile("cp.async.wait_group 1;" ::: "memory");
        } else {
            asm volatile("cp.async.wait_group 0;" ::: "memory");
        }
        __syncthreads();

        uint32_t sb = sbase + (c & 1) * FBUF;

        #pragma unroll
        for (int j = 0; j < 8; j++) { s[j][0] = s[j][1] = s[j][2] = s[j][3] = 0.f; }
        #pragma unroll
        for (int kb = 0; kb < 4; kb++) {
            uint32_t kh[4][4];
            #pragma unroll
            for (int j = 0; j < 4; j++)
                ldsm_x4(kh[j], sb + ((j * 16 + brow) * 72 + kb * 16 + bcg * 8) * 2);
            #pragma unroll
            for (int j = 0; j < 8; j++)
                mma16816(s[j], aq[kb], kh[j >> 1][(j & 1) * 2], kh[j >> 1][(j & 1) * 2 + 1]);
        }

        // ---- online softmax, log2 domain, hardware EX2 ----
        float mx0 = s[0][0], mx1 = s[0][2];
        #pragma unroll
        for (int j = 0; j < 8; j++) {
            mx0 = fmaxf(mx0, fmaxf(s[j][0], s[j][1]));
            mx1 = fmaxf(mx1, fmaxf(s[j][2], s[j][3]));
        }
        mx0 = fmaxf(mx0, __shfl_xor_sync(0xffffffffu, mx0, 1));
        mx0 = fmaxf(mx0, __shfl_xor_sync(0xffffffffu, mx0, 2));
        mx1 = fmaxf(mx1, __shfl_xor_sync(0xffffffffu, mx1, 1));
        mx1 = fmaxf(mx1, __shfl_xor_sync(0xffffffffu, mx1, 2));
        float mn0 = fmaxf(m0, mx0), mn1 = fmaxf(m1, mx1);
        float al0 = hexp2(m0 - mn0), al1 = hexp2(m1 - mn1);
        m0 = mn0; m1 = mn1;
        float sum0 = 0.f, sum1 = 0.f;
        #pragma unroll
        for (int j = 0; j < 8; j++) {
            s[j][0] = hexp2(s[j][0] - mn0);
            s[j][1] = hexp2(s[j][1] - mn0);
            s[j][2] = hexp2(s[j][2] - mn1);
            s[j][3] = hexp2(s[j][3] - mn1);
            sum0 += s[j][0] + s[j][1];
            sum1 += s[j][2] + s[j][3];
        }
        sum0 += __shfl_xor_sync(0xffffffffu, sum0, 1);
        sum0 += __shfl_xor_sync(0xffffffffu, sum0, 2);
        sum1 += __shfl_xor_sync(0xffffffffu, sum1, 1);
        sum1 += __shfl_xor_sync(0xffffffffu, sum1, 2);
        l0 = l0 * al0 + sum0;
        l1 = l1 * al1 + sum1;
        #pragma unroll
        for (int j = 0; j < 8; j++) {
            o[j][0] *= al0; o[j][1] *= al0; o[j][2] *= al1; o[j][3] *= al1;
        }

        #pragma unroll
        for (int kb = 0; kb < 4; kb++) {
            uint32_t ph[4];
            ph[0] = pack_h(s[2 * kb][0],     s[2 * kb][1]);
            ph[1] = pack_h(s[2 * kb][2],     s[2 * kb][3]);
            ph[2] = pack_h(s[2 * kb + 1][0], s[2 * kb + 1][1]);
            ph[3] = pack_h(s[2 * kb + 1][2], s[2 * kb + 1][3]);

            uint32_t vh[4][4];
            #pragma unroll
            for (int j = 0; j < 4; j++)
                ldsm_x4(vh[j], sb + FT + ((j * 16 + brow) * 72 + kb * 16 + bcg * 8) * 2);
            #pragma unroll
            for (int j = 0; j < 8; j++)
                mma16816(o[j], ph, vh[j >> 1][(j & 1) * 2], vh[j >> 1][(j & 1) * 2 + 1]);
        }
        __syncthreads();
    }

    float i0 = 1.f / l0, i1 = 1.f / l1;
    int r0 = qt * 128 + w * 16 + (lane >> 2);
    #pragma unroll
    for (int j = 0; j < 8; j++) {
        int n = h * 64 + j * 8 + (lane & 3) * 2;
        size_t o0 = ((size_t)(b * SS) + r0) * HID + n;
        size_t o1 = o0 + 8 * HID;
        *(uint32_t*)&g_ah[o0] = pack_h(o[j][0] * i0, o[j][1] * i0);
        *(uint32_t*)&g_ah[o1] = pack_h(o[j][2] * i1, o[j][3] * i1);
    }
}

// ==================== launch (serial) ====================
extern "C" void kernel_launch(void* const* d_in, const int* in_sizes, int n_in,
                              void* d_out, int out_size)
{
    const float* x  = (const float*)d_in[0];
    const float* Wq = (const float*)d_in[1];
    const float* Wk = (const float*)d_in[2];
    const float* Wv = (const float*)d_in[3];
    const float* Wo = (const float*)d_in[4];
    const float* W1 = (const float*)d_in[5];
    const float* b1 = (const float*)d_in[6];
    const float* W2 = (const float*)d_in[7];
    const float* b2 = (const float*)d_in[8];
    float* out = (float*)d_out;

    cudaFuncSetAttribute(mm_mma_kernel<0>, cudaFuncAttributeMaxDynamicSharedMemorySize, SMEM_MM);
    cudaFuncSetAttribute(mm_mma_kernel<1>, cudaFuncAttributeMaxDynamicSharedMemorySize, SMEM_MM);
    cudaFuncSetAttribute(flash_mma_kernel, cudaFuncAttributeMaxDynamicSharedMemorySize, SMEM_F);
    cudaFuncSetAttribute(repo_gemm_kernel, cudaFuncAttributeMaxDynamicSharedMemorySize, RG_SMEM);

    conv_x_kernel<<<4096, 256>>>(x);
    conv_wT_kernel<<<dim3(32, 32, 5), dim3(32, 32)>>>(Wq, Wk, Wv, Wo, W1);
    repo_gemm_kernel<<<dim3(4, 32), 256, RG_SMEM>>>();
    repo_finish_kernel<<<1024, 128>>>(b1, W2, b2);
    scan_kernel<<<2, 1024>>>();
    angles_kernel<<<512, 256>>>();
    mm_mma_kernel<0><<<dim3(8, 32, 3), 256, SMEM_MM>>>(nullptr);
    flash_mma_kernel<<<dim3(16, 32), 256, SMEM_F>>>();
    mm_mma_kernel<1><<<dim3(8, 32), 256, SMEM_MM>>>(out);
}

// round 15
// speedup vs baseline: 1.1338x; 1.0077x over previous
#include <cuda_runtime.h>
#include <cuda_fp16.h>
#include <math.h>
#include <stdint.h>

#define BB   2
#define SS   2048
#define HH   16
#define DD   64
#define HID  1024
#define PD   128

// ---------------- scratch (device globals — no allocation allowed) ----------------
__device__ float  g_sp[BB*SS];
__device__ double g_posd[BB*SS];
__device__ __align__(256) float g_cos[BB*SS*32];
__device__ __align__(256) float g_sin[BB*SS*32];
// fp16 operands
__device__ __align__(256) __half g_xh[BB*SS*HID];        // x fp16 (hi)
__device__ __align__(256) __half g_xl[BB*SS*HID];        // x fp16 (lo residual)
__device__ __align__(256) __half g_ah[BB*SS*HID];        // attention out fp16
__device__ __align__(256) __half g_wt[4*HID*HID];        // W^T (n,k) fp16, z = q,k,v,o
__device__ __align__(256) __half g_w1h[PD*HID];          // W1^T (p,d) fp16 hi
__device__ __align__(256) __half g_w1l[PD*HID];          // W1^T (p,d) fp16 lo
__device__ __align__(256) float  g_H[4*BB*SS*PD];        // repo H partials, 4 k-slices
__device__ __align__(256) __half g_q[BB*HH*SS*DD];       // (b,h,s,d), RoPE'd, scaled 0.125*log2e
__device__ __align__(256) __half g_k[BB*HH*SS*DD];       // (b,h,s,d), RoPE'd
__device__ __align__(256) __half g_vt[BB*HH*DD*SS];      // (b,h,d,s)  V^T

// ==================== helpers ====================
__device__ __forceinline__ uint32_t smem_u32(const void* p) {
    uint32_t a;
    asm("{ .reg .u64 t; cvta.to.shared.u64 t, %1; cvt.u32.u64 %0, t; }" : "=r"(a) : "l"(p));
    return a;
}
__device__ __forceinline__ void cp_async16(uint32_t dst, const void* src) {
    asm volatile("cp.async.cg.shared.global [%0], [%1], 16;" :: "r"(dst), "l"(src));
}
__device__ __forceinline__ void cp_commit() {
    asm volatile("cp.async.commit_group;" ::: "memory");
}
__device__ __forceinline__ void ldsm_x4(uint32_t* r, uint32_t addr) {
    asm volatile("ldmatrix.sync.aligned.m8n8.x4.shared.b16 {%0,%1,%2,%3}, [%4];"
                 : "=r"(r[0]), "=r"(r[1]), "=r"(r[2]), "=r"(r[3]) : "r"(addr));
}
__device__ __forceinline__ void mma16816(float* c, const uint32_t* a, uint32_t b0, uint32_t b1) {
    asm volatile(
        "mma.sync.aligned.m16n8k16.row.col.f32.f16.f16.f32 "
        "{%0,%1,%2,%3}, {%4,%5,%6,%7}, {%8,%9}, {%0,%1,%2,%3};"
        : "+f"(c[0]), "+f"(c[1]), "+f"(c[2]), "+f"(c[3])
        : "r"(a[0]), "r"(a[1]), "r"(a[2]), "r"(a[3]), "r"(b0), "r"(b1));
}
// pack two fp32 -> f16x2 (first arg -> low half)
__device__ __forceinline__ uint32_t pack_h(float lo, float hi) {
    uint32_t r;
    asm("cvt.rn.f16x2.f32 %0, %2, %1;" : "=r"(r) : "f"(lo), "f"(hi));
    return r;
}
// hardware exp2: single EX2 via MUFU (no log2e multiply)
__device__ __forceinline__ float hexp2(float x) {
    float r;
    asm("ex2.approx.f32 %0, %1;" : "=f"(r) : "f"(x));
    return r;
}

// ==================== fp32 x -> fp16 hi/lo ====================
__global__ __launch_bounds__(256) void conv_x_kernel(const float* __restrict__ src)
{
    int idx = (blockIdx.x * 256 + threadIdx.x) * 4;
    float4 v = *(const float4*)&src[idx];
    __half hx = __float2half(v.x), hy = __float2half(v.y);
    __half hz = __float2half(v.z), hw = __float2half(v.w);
    uint2 H, L;
    H.x = pack_h(v.x, v.y);
    H.y = pack_h(v.z, v.w);
    L.x = pack_h(v.x - __half2float(hx), v.y - __half2float(hy));
    L.y = pack_h(v.z - __half2float(hz), v.w - __half2float(hw));
    *(uint2*)&g_xh[idx] = H;
    *(uint2*)&g_xl[idx] = L;
}

// ==================== W transposes -> fp16 ====================
__global__ void conv_wT_kernel(const float* __restrict__ Wq, const float* __restrict__ Wk,
                               const float* __restrict__ Wv, const float* __restrict__ Wo,
                               const float* __restrict__ W1)
{
    __shared__ float t[32][33];
    int z = blockIdx.z;
    if (z == 4) {
        if (blockIdx.x >= 4) return;
        int n0 = blockIdx.x * 32, k0 = blockIdx.y * 32;   // n = p, k = d
        t[threadIdx.y][threadIdx.x] = W1[(size_t)(k0 + threadIdx.y) * PD + n0 + threadIdx.x];
        __syncthreads();
        float v = t[threadIdx.x][threadIdx.y];
        size_t o = (size_t)(n0 + threadIdx.y) * HID + k0 + threadIdx.x;
        __half h = __float2half(v);
        g_w1h[o] = h;
        g_w1l[o] = __float2half(v - __half2float(h));
        return;
    }
    const float* W = (z == 0) ? Wq : (z == 1) ? Wk : (z == 2) ? Wv : Wo;
    int n0 = blockIdx.x * 32, k0 = blockIdx.y * 32;
    t[threadIdx.y][threadIdx.x] = W[(size_t)(k0 + threadIdx.y) * HID + n0 + threadIdx.x];
    __syncthreads();
    float v = t[threadIdx.x][threadIdx.y];
    size_t o = ((size_t)z << 20) + (size_t)(n0 + threadIdx.y) * HID + k0 + threadIdx.x;
    g_wt[o] = __float2half(v);
}

// ==================== repo stage-1 GEMM: fp16 3-pass, pipelined ====================
#define RT       18432                 // 128 rows * 144 B
#define RG_BUF   (4 * RT)
#define RG_SMEM  (2 * RG_BUF)

__global__ __launch_bounds__(256) void repo_gemm_kernel()
{
    extern __shared__ __align__(128) char smem[];
    uint32_t sbase = smem_u32(smem);
    int tid = threadIdx.x, lane = tid & 31, wid = tid >> 5;
    int wm = wid & 3, wn = wid >> 2;

    int ks0 = blockIdx.x * 256;
    int m0  = blockIdx.y * 128;
    const __half* Ah = g_xh  + (size_t)m0 * HID + ks0;
    const __half* Al = g_xl  + (size_t)m0 * HID + ks0;
    const __half* Bh = g_w1h + ks0;
    const __half* Bl = g_w1l + ks0;
    const __half* bases[4] = {Ah, Al, Bh, Bl};

    float acc[2][8][4];
    #pragma unroll
    for (int i = 0; i < 2; i++)
        #pragma unroll
        for (int j = 0; j < 8; j++)
            #pragma unroll
            for (int q = 0; q < 4; q++) acc[i][j][q] = 0.f;

    int arow = lane & 15,  acg = lane >> 4;
    int brow = (lane & 7) + ((lane >> 4) << 3);
    int bcg  = (lane >> 3) & 1;

    #pragma unroll
    for (int it = 0; it < 16; it++) {
        int lin = it * 256 + tid;
        int tile = lin >> 10, idx = lin & 1023, r = idx >> 3, seg = idx & 7;
        cp_async16(sbase + tile * RT + r * 144 + seg * 16,
                   bases[tile] + (size_t)r * HID + seg * 8);
    }
    cp_commit();

    for (int c = 0; c < 4; c++) {
        if (c + 1 < 4) {
            int k0 = (c + 1) * 64;
            uint32_t sb = sbase + ((c + 1) & 1) * RG_BUF;
            #pragma unroll
            for (int it = 0; it < 16; it++) {
                int lin = it * 256 + tid;
                int tile = lin >> 10, idx = lin & 1023, r = idx >> 3, seg = idx & 7;
                cp_async16(sb + tile * RT + r * 144 + seg * 16,
                           bases[tile] + (size_t)r * HID + k0 + seg * 8);
            }
            cp_commit();
            asm volatile("cp.async.wait_group 1;" ::: "memory");
        } else {
            asm volatile("cp.async.wait_group 0;" ::: "memory");
        }
        __syncthreads();

        uint32_t sb = sbase + (c & 1) * RG_BUF;
        uint32_t sAh = sb, sAl = sb + RT, sBh = sb + 2 * RT, sBl = sb + 3 * RT;
        #pragma unroll
        for (int ks = 0; ks < 4; ks++) {
            uint32_t ah[2][4], al[2][4], bh[4][4], bl[4][4];
            #pragma unroll
            for (int i = 0; i < 2; i++) {
                ldsm_x4(ah[i], sAh + ((wm * 32 + i * 16 + arow) * 72 + ks * 16 + acg * 8) * 2);
                ldsm_x4(al[i], sAl + ((wm * 32 + i * 16 + arow) * 72 + ks * 16 + acg * 8) * 2);
            }
            #pragma unroll
            for (int j = 0; j < 4; j++) {
                ldsm_x4(bh[j], sBh + ((wn * 64 + j * 16 + brow) * 72 + ks * 16 + bcg * 8) * 2);
                ldsm_x4(bl[j], sBl + ((wn * 64 + j * 16 + brow) * 72 + ks * 16 + bcg * 8) * 2);
            }
            #pragma unroll
            for (int i = 0; i < 2; i++)
                #pragma unroll
                for (int j = 0; j < 8; j++) {
                    mma16816(acc[i][j], ah[i], bh[j >> 1][(j & 1) * 2], bh[j >> 1][(j & 1) * 2 + 1]);
                    mma16816(acc[i][j], ah[i], bl[j >> 1][(j & 1) * 2], bl[j >> 1][(j & 1) * 2 + 1]);
                    mma16816(acc[i][j], al[i], bh[j >> 1][(j & 1) * 2], bh[j >> 1][(j & 1) * 2 + 1]);
                }
        }
        __syncthreads();
    }

    float* Hs = g_H + (size_t)blockIdx.x * (BB * SS * PD);
    #pragma unroll
    for (int i = 0; i < 2; i++)
        #pragma unroll
        for (int j = 0; j < 8; j++) {
            int n = wn * 64 + j * 8 + (lane & 3) * 2;
            #pragma unroll
            for (int hf = 0; hf < 2; hf++) {
                int m = m0 + wm * 32 + i * 16 + (lane >> 2) + hf * 8;
                *(float2*)(Hs + (size_t)m * PD + n) =
                    make_float2(acc[i][j][hf * 2], acc[i][j][hf * 2 + 1]);
            }
        }
}

// ==================== repo finish ====================
__global__ __launch_bounds__(128) void repo_finish_kernel(
    const float* __restrict__ b1, const float* __restrict__ W2, const float* __restrict__ b2)
{
    int warp = threadIdx.x >> 5, lane = threadIdx.x & 31;
    int r = blockIdx.x * 4 + warp;
    float4 hv = make_float4(0.f, 0.f, 0.f, 0.f);
    #pragma unroll
    for (int sl = 0; sl < 4; sl++) {
        float4 t = *(const float4*)&g_H[(size_t)sl * (BB * SS * PD) + (size_t)r * PD + lane * 4];
        hv.x += t.x; hv.y += t.y; hv.z += t.z; hv.w += t.w;
    }
    float4 bb = *(const float4*)&b1[lane * 4];
    float4 w2 = *(const float4*)&W2[lane * 4];
    float vv[4] = {hv.x + bb.x, hv.y + bb.y, hv.z + bb.z, hv.w + bb.w};
    float ww[4] = {w2.x, w2.y, w2.z, w2.w};
    float sum = 0.f;
    #pragma unroll
    for (int q = 0; q < 4; q++) {
        float z = vv[q];
        float g = 0.5f * z * (1.f + tanhf(0.7978845608028654f * (z + 0.044715f * z * z * z)));
        sum += g * ww[q];
    }
    #pragma unroll
    for (int off = 16; off; off >>= 1) sum += __shfl_xor_sync(0xffffffffu, sum, off);
    if (lane == 0) {
        float raw = sum + b2[0];
        g_sp[r] = fmaxf(raw, 0.f) + log1pf(expf(-fabsf(raw)));
    }
}

// ==================== fp64 scan ====================
__global__ __launch_bounds__(1024) void scan_kernel()
{
    __shared__ double sc[1024];
    int b = blockIdx.x, t = threadIdx.x;
    float a0 = g_sp[b * SS + 2 * t];
    float a1 = g_sp[b * SS + 2 * t + 1];
    sc[t] = (double)a0 + (double)a1;
    __syncthreads();
    for (int off = 1; off < 1024; off <<= 1) {
        double v = (t >= off) ? sc[t - off] : 0.0;
        __syncthreads();
        sc[t] += v;
        __syncthreads();
    }
    double excl = (t == 0) ? 0.0 : sc[t - 1];
    g_posd[b * SS + 2 * t]     = excl + (double)a0;
    g_posd[b * SS + 2 * t + 1] = excl + (double)a0 + (double)a1;
}

// ==================== angles ====================
__global__ __launch_bounds__(256) void angles_kernel()
{
    int idx = blockIdx.x * 256 + threadIdx.x;
    int j = idx & 31, bs = idx >> 5;
    double f   = exp(((double)(-2 * j) / 64.0) * 9.210340371976184);
    double ang = g_posd[bs] * f;
    const double twopi = 6.283185307179586476925286766559;
    ang -= floor(ang * (1.0 / twopi)) * twopi;
    float af = (float)ang;
    g_cos[idx] = cosf(af);
    g_sin[idx] = sinf(af);
}

// ==================== mma.sync fp16 GEMM: 128x128 tile, BK=64, 256 threads, occ 2 ====
// MODE 0: A = g_xh, B = wt[z], z = 0..2; fused epilogue:
//          z=0/1 -> RoPE -> g_q / g_k (Q scaled 0.125*log2e for exp2 softmax)
//          z=2   -> transpose -> g_vt (b,h,d,s)
// MODE 1: A = g_ah, B = wt[3]; row-major fp32 -> outp
#define TILE_B   18432
#define BUF_B    (2 * TILE_B)
#define SMEM_MM  (2 * BUF_B)

template<int MODE>
__global__ __launch_bounds__(256, 2) void mm_mma_kernel(float* __restrict__ outp)
{
    extern __shared__ __align__(128) char smem[];
    uint32_t sbase = smem_u32(smem);
    int tid = threadIdx.x;
    int lane = tid & 31, wid = tid >> 5;
    int wm = wid & 3, wn = wid >> 2;

    int n0 = blockIdx.x * 128, m0 = blockIdx.y * 128;
    int z  = (MODE == 0) ? (int)blockIdx.z : 3;
    const __half* A = ((MODE == 0) ? g_xh : g_ah) + (size_t)m0 * HID;
    const __half* B = g_wt + ((size_t)z << 20) + (size_t)n0 * HID;

    float acc[2][8][4];
    #pragma unroll
    for (int i = 0; i < 2; i++)
        #pragma unroll
        for (int j = 0; j < 8; j++)
            #pragma unroll
            for (int q = 0; q < 4; q++) acc[i][j][q] = 0.f;

    int arow = lane & 15,  acg = lane >> 4;
    int brow = (lane & 7) + ((lane >> 4) << 3);
    int bcg  = (lane >> 3) & 1;

    {
        const __half* bases[2] = {A, B};
        #pragma unroll
        for (int it = 0; it < 8; it++) {
            int lin = it * 256 + tid;
            int tile = lin >> 10, idx = lin & 1023, r = idx >> 3, seg = idx & 7;
            cp_async16(sbase + tile * TILE_B + r * 144 + seg * 16,
                       bases[tile] + (size_t)r * HID + seg * 8);
        }
        cp_commit();
    }

    for (int c = 0; c < 16; c++) {
        if (c + 1 < 16) {
            int k0 = (c + 1) * 64;
            uint32_t sb = sbase + ((c + 1) & 1) * BUF_B;
            const __half* bases[2] = {A, B};
            #pragma unroll
            for (int it = 0; it < 8; it++) {
                int lin = it * 256 + tid;
                int tile = lin >> 10, idx = lin & 1023, r = idx >> 3, seg = idx & 7;
                cp_async16(sb + tile * TILE_B + r * 144 + seg * 16,
                           bases[tile] + (size_t)r * HID + k0 + seg * 8);
            }
            cp_commit();
            asm volatile("cp.async.wait_group 1;" ::: "memory");
        } else {
            asm volatile("cp.async.wait_group 0;" ::: "memory");
        }
        __syncthreads();

        uint32_t sb = sbase + (c & 1) * BUF_B;
        uint32_t sA = sb, sB = sb + TILE_B;

        #pragma unroll
        for (int ks = 0; ks < 4; ks++) {
            uint32_t a[2][4], bh[4][4];
            #pragma unroll
            for (int i = 0; i < 2; i++)
                ldsm_x4(a[i], sA + ((wm * 32 + i * 16 + arow) * 72 + ks * 16 + acg * 8) * 2);
            #pragma unroll
            for (int j = 0; j < 4; j++)
                ldsm_x4(bh[j], sB + ((wn * 64 + j * 16 + brow) * 72 + ks * 16 + bcg * 8) * 2);
            #pragma unroll
            for (int i = 0; i < 2; i++)
                #pragma unroll
                for (int j = 0; j < 8; j++)
                    mma16816(acc[i][j], a[i], bh[j >> 1][(j & 1) * 2], bh[j >> 1][(j & 1) * 2 + 1]);
        }
        __syncthreads();
    }

    // ---- epilogue ----
    if (MODE == 1) {
        #pragma unroll
        for (int i = 0; i < 2; i++)
            #pragma unroll
            for (int j = 0; j < 8; j++) {
                int n = n0 + wn * 64 + j * 8 + (lane & 3) * 2;
                #pragma unroll
                for (int hf = 0; hf < 2; hf++) {
                    int m = m0 + wm * 32 + i * 16 + (lane >> 2) + hf * 8;
                    *(float2*)(outp + (size_t)m * HID + n) =
                        make_float2(acc[i][j][hf * 2], acc[i][j][hf * 2 + 1]);
                }
            }
        return;
    }

    int h = (n0 + wn * 64) >> 6;
    if (z == 2) {
        #pragma unroll
        for (int i = 0; i < 2; i++)
            #pragma unroll
            for (int hf = 0; hf < 2; hf++) {
                int m = m0 + wm * 32 + i * 16 + (lane >> 2) + hf * 8;
                int b = m >> 11, s = m & 2047;
                size_t basev = ((size_t)(b * HH + h)) * DD * SS + s;
                #pragma unroll
                for (int j = 0; j < 8; j++) {
                    int d = j * 8 + (lane & 3) * 2;
                    g_vt[basev + (size_t)d * SS]       = __float2half(acc[i][j][hf * 2]);
                    g_vt[basev + (size_t)(d + 1) * SS] = __float2half(acc[i][j][hf * 2 + 1]);
                }
            }
    } else {
        __half* dst = (z == 0) ? g_q : g_k;
        // Q scale folds 1/sqrt(64) * log2(e) so flash softmax works in exp2 domain
        float qscale = (z == 0) ? 0.18033688011112042f : 1.0f;
        #pragma unroll
        for (int i = 0; i < 2; i++)
            #pragma unroll
            for (int hf = 0; hf < 2; hf++) {
                int m = m0 + wm * 32 + i * 16 + (lane >> 2) + hf * 8;
                int b = m >> 11, s = m & 2047;
                size_t baseo = ((size_t)((b * HH + h) * SS + s)) * DD;
                int cbase = (b * SS + s) * 32;
                #pragma unroll
                for (int j = 0; j < 4; j++) {
                    int d = j * 8 + (lane & 3) * 2;
                    float c0 = g_cos[cbase + d],     sn0 = g_sin[cbase + d];
                    float c1 = g_cos[cbase + d + 1], sn1 = g_sin[cbase + d + 1];
                    float t1a = acc[i][j][hf * 2],     t1b = acc[i][j][hf * 2 + 1];
                    float t2a = acc[i][j + 4][hf * 2], t2b = acc[i][j + 4][hf * 2 + 1];
                    float ra  = qscale * (t1a * c0 - t2a * sn0);
                    float rb  = qscale * (t1b * c1 - t2b * sn1);
                    float r2a = qscale * (t1a * sn0 + t2a * c0);
                    float r2b = qscale * (t1b * sn1 + t2b * c1);
                    *(uint32_t*)&dst[baseo + d]      = pack_h(ra, rb);
                    *(uint32_t*)&dst[baseo + d + 32] = pack_h(r2a, r2b);
                }
            }
    }
}

// ==================== Flash attention: BQ=128, BKV=64, exp2 (MUFU) softmax ====================
#define FT     9216
#define FBUF   (2 * FT)
#define SMEM_F (2 * FBUF)

__global__ __launch_bounds__(256, 2) void flash_mma_kernel()
{
    extern __shared__ __align__(128) char fsm[];
    uint32_t sbase = smem_u32(fsm);
    int tid = threadIdx.x, lane = tid & 31, w = tid >> 5;
    int qt = blockIdx.x, bh = blockIdx.y;
    int b = bh >> 4, h = bh & 15;

    const __half* Q  = g_q  + ((size_t)bh * SS + qt * 128) * DD;
    const __half* K  = g_k  + (size_t)bh * SS * DD;
    const __half* Vt = g_vt + (size_t)bh * DD * SS;

    int arow = lane & 15, acg = lane >> 4;
    int brow = (lane & 7) + ((lane >> 4) << 3), bcg = (lane >> 3) & 1;

    #pragma unroll
    for (int it = 0; it < 4; it++) {
        int lin = it * 256 + tid;
        int r = lin >> 3, seg = lin & 7;
        cp_async16(sbase + r * 144 + seg * 16, Q + (size_t)r * DD + seg * 8);
    }
    cp_commit();
    asm volatile("cp.async.wait_group 0;" ::: "memory");
    __syncthreads();
    uint32_t aq[4][4];
    #pragma unroll
    for (int kb = 0; kb < 4; kb++)
        ldsm_x4(aq[kb], sbase + ((w * 16 + arow) * 72 + kb * 16 + acg * 8) * 2);
    __syncthreads();

    float s[8][4], o[8][4];
    #pragma unroll
    for (int j = 0; j < 8; j++)
        #pragma unroll
        for (int q = 0; q < 4; q++) o[j][q] = 0.f;
    float m0 = -1e30f, m1 = -1e30f, l0 = 0.f, l1 = 0.f;

    {
        #pragma unroll
        for (int it = 0; it < 4; it++) {
            int lin = it * 256 + tid;
            int tile = lin >> 9, idx = lin & 511;
            int r = idx >> 3, seg = idx & 7;
            const __half* src = (tile == 0) ? K  + (size_t)r * DD + seg * 8
                                            : Vt + (size_t)r * SS + seg * 8;
            cp_async16(sbase + tile * FT + r * 144 + seg * 16, src);
        }
        cp_commit();
    }

    for (int c = 0; c < 32; c++) {
        if (c + 1 < 32) {
            int kbase = (c + 1) * 64;
            uint32_t sb = sbase + ((c + 1) & 1) * FBUF;
            #pragma unroll
            for (int it = 0; it < 4; it++) {
                int lin = it * 256 + tid;
                int tile = lin >> 9, idx = lin & 511;
                int r = idx >> 3, seg = idx & 7;
                const __half* src = (tile == 0) ? K  + (size_t)(kbase + r) * DD + seg * 8
                                                : Vt + (size_t)r * SS + kbase + seg * 8;
                cp_async16(sb + tile * FT + r * 144 + seg * 16, src);
            }
            cp_commit();
            asm volatile("cp.async.wait_group 1;" ::: "memory");
        } else {
            asm volatile("cp.async.wait_group 0;" ::: "memory");
        }
        __syncthreads();

        uint32_t sb = sbase + (c & 1) * FBUF;

        #pragma unroll
        for (int j = 0; j < 8; j++) { s[j][0] = s[j][1] = s[j][2] = s[j][3] = 0.f; }
        #pragma unroll
        for (int kb = 0; kb < 4; kb++) {
            uint32_t kh[4][4];
            #pragma unroll
            for (int j = 0; j < 4; j++)
                ldsm_x4(kh[j], sb + ((j * 16 + brow) * 72 + kb * 16 + bcg * 8) * 2);
            #pragma unroll
            for (int j = 0; j < 8; j++)
                mma16816(s[j], aq[kb], kh[j >> 1][(j & 1) * 2], kh[j >> 1][(j & 1) * 2 + 1]);
        }

        // ---- online softmax, log2 domain, hardware EX2 ----
        float mx0 = s[0][0], mx1 = s[0][2];
        #pragma unroll
        for (int j = 0; j < 8; j++) {
            mx0 = fmaxf(mx0, fmaxf(s[j][0], s[j][1]));
            mx1 = fmaxf(mx1, fmaxf(s[j][2], s[j][3]));
        }
        mx0 = fmaxf(mx0, __shfl_xor_sync(0xffffffffu, mx0, 1));
        mx0 = fmaxf(mx0, __shfl_xor_sync(0xffffffffu, mx0, 2));
        mx1 = fmaxf(mx1, __shfl_xor_sync(0xffffffffu, mx1, 1));
        mx1 = fmaxf(mx1, __shfl_xor_sync(0xffffffffu, mx1, 2));
        float mn0 = fmaxf(m0, mx0), mn1 = fmaxf(m1, mx1);
        float al0 = hexp2(m0 - mn0), al1 = hexp2(m1 - mn1);
        m0 = mn0; m1 = mn1;
        float sum0 = 0.f, sum1 = 0.f;
        #pragma unroll
        for (int j = 0; j < 8; j++) {
            s[j][0] = hexp2(s[j][0] - mn0);
            s[j][1] = hexp2(s[j][1] - mn0);
            s[j][2] = hexp2(s[j][2] - mn1);
            s[j][3] = hexp2(s[j][3] - mn1);
            sum0 += s[j][0] + s[j][1];
            sum1 += s[j][2] + s[j][3];
        }
        sum0 += __shfl_xor_sync(0xffffffffu, sum0, 1);
        sum0 += __shfl_xor_sync(0xffffffffu, sum0, 2);
        sum1 += __shfl_xor_sync(0xffffffffu, sum1, 1);
        sum1 += __shfl_xor_sync(0xffffffffu, sum1, 2);
        l0 = l0 * al0 + sum0;
        l1 = l1 * al1 + sum1;
        #pragma unroll
        for (int j = 0; j < 8; j++) {
            o[j][0] *= al0; o[j][1] *= al0; o[j][2] *= al1; o[j][3] *= al1;
        }

        #pragma unroll
        for (int kb = 0; kb < 4; kb++) {
            uint32_t ph[4];
            ph[0] = pack_h(s[2 * kb][0],     s[2 * kb][1]);
            ph[1] = pack_h(s[2 * kb][2],     s[2 * kb][3]);
            ph[2] = pack_h(s[2 * kb + 1][0], s[2 * kb + 1][1]);
            ph[3] = pack_h(s[2 * kb + 1][2], s[2 * kb + 1][3]);

            uint32_t vh[4][4];
            #pragma unroll
            for (int j = 0; j < 4; j++)
                ldsm_x4(vh[j], sb + FT + ((j * 16 + brow) * 72 + kb * 16 + bcg * 8) * 2);
            #pragma unroll
            for (int j = 0; j < 8; j++)
                mma16816(o[j], ph, vh[j >> 1][(j & 1) * 2], vh[j >> 1][(j & 1) * 2 + 1]);
        }
        __syncthreads();
    }

    float i0 = 1.f / l0, i1 = 1.f / l1;
    int r0 = qt * 128 + w * 16 + (lane >> 2);
    #pragma unroll
    for (int j = 0; j < 8; j++) {
        int n = h * 64 + j * 8 + (lane & 3) * 2;
        size_t o0 = ((size_t)(b * SS) + r0) * HID + n;
        size_t o1 = o0 + 8 * HID;
        *(uint32_t*)&g_ah[o0] = pack_h(o[j][0] * i0, o[j][1] * i0);
        *(uint32_t*)&g_ah[o1] = pack_h(o[j][2] * i1, o[j][3] * i1);
    }
}

// ==================== launch (serial) ====================
extern "C" void kernel_launch(void* const* d_in, const int* in_sizes, int n_in,
                              void* d_out, int out_size)
{
    const float* x  = (const float*)d_in[0];
    const float* Wq = (const float*)d_in[1];
    const float* Wk = (const float*)d_in[2];
    const float* Wv = (const float*)d_in[3];
    const float* Wo = (const float*)d_in[4];
    const float* W1 = (const float*)d_in[5];
    const float* b1 = (const float*)d_in[6];
    const float* W2 = (const float*)d_in[7];
    const float* b2 = (const float*)d_in[8];
    float* out = (float*)d_out;

    cudaFuncSetAttribute(mm_mma_kernel<0>, cudaFuncAttributeMaxDynamicSharedMemorySize, SMEM_MM);
    cudaFuncSetAttribute(mm_mma_kernel<1>, cudaFuncAttributeMaxDynamicSharedMemorySize, SMEM_MM);
    cudaFuncSetAttribute(flash_mma_kernel, cudaFuncAttributeMaxDynamicSharedMemorySize, SMEM_F);
    cudaFuncSetAttribute(repo_gemm_kernel, cudaFuncAttributeMaxDynamicSharedMemorySize, RG_SMEM);

    conv_x_kernel<<<4096, 256>>>(x);
    conv_wT_kernel<<<dim3(32, 32, 5), dim3(32, 32)>>>(Wq, Wk, Wv, Wo, W1);
    repo_gemm_kernel<<<dim3(4, 32), 256, RG_SMEM>>>();
    repo_finish_kernel<<<1024, 128>>>(b1, W2, b2);
    scan_kernel<<<2, 1024>>>();
    angles_kernel<<<512, 256>>>();
    mm_mma_kernel<0><<<dim3(8, 32, 3), 256, SMEM_MM>>>(nullptr);
    flash_mma_kernel<<<dim3(16, 32), 256, SMEM_F>>>();
    mm_mma_kernel<1><<<dim3(8, 32), 256, SMEM_MM>>>(out);
}

// round 16
// speedup vs baseline: 1.1667x; 1.0291x over previous
#include <cuda_runtime.h>
#include <cuda_fp16.h>
#include <math.h>
#include <stdint.h>

#define BB   2
#define SS   2048
#define HH   16
#define DD   64
#define HID  1024
#define PD   128

// ---------------- scratch (device globals — no allocation allowed) ----------------
__device__ float  g_sp[BB*SS];
__device__ double g_posd[BB*SS];
__device__ __align__(256) float g_cos[BB*SS*32];
__device__ __align__(256) float g_sin[BB*SS*32];
// fp16 operands
__device__ __align__(256) __half g_xh[BB*SS*HID];        // x fp16 (hi)
__device__ __align__(256) __half g_xl[BB*SS*HID];        // x fp16 (lo residual)
__device__ __align__(256) __half g_ah[BB*SS*HID];        // attention out fp16
__device__ __align__(256) __half g_wt[4*HID*HID];        // W^T (n,k) fp16, z = q,k,v,o
__device__ __align__(256) __half g_w1h[PD*HID];          // W1^T (p,d) fp16 hi
__device__ __align__(256) __half g_w1l[PD*HID];          // W1^T (p,d) fp16 lo
__device__ __align__(256) float  g_H[4*BB*SS*PD];        // repo H partials, 4 k-slices
__device__ __align__(256) __half g_q[BB*HH*SS*DD];       // (b,h,s,d), RoPE'd, scaled 0.125*log2e
__device__ __align__(256) __half g_k[BB*HH*SS*DD];       // (b,h,s,d), RoPE'd
__device__ __align__(256) __half g_vt[BB*HH*DD*SS];      // (b,h,d,s)  V^T

// ==================== helpers ====================
__device__ __forceinline__ uint32_t smem_u32(const void* p) {
    uint32_t a;
    asm("{ .reg .u64 t; cvta.to.shared.u64 t, %1; cvt.u32.u64 %0, t; }" : "=r"(a) : "l"(p));
    return a;
}
__device__ __forceinline__ void cp_async16(uint32_t dst, const void* src) {
    asm volatile("cp.async.cg.shared.global [%0], [%1], 16;" :: "r"(dst), "l"(src));
}
__device__ __forceinline__ void cp_commit() {
    asm volatile("cp.async.commit_group;" ::: "memory");
}
__device__ __forceinline__ void ldsm_x4(uint32_t* r, uint32_t addr) {
    asm volatile("ldmatrix.sync.aligned.m8n8.x4.shared.b16 {%0,%1,%2,%3}, [%4];"
                 : "=r"(r[0]), "=r"(r[1]), "=r"(r[2]), "=r"(r[3]) : "r"(addr));
}
__device__ __forceinline__ void mma16816(float* c, const uint32_t* a, uint32_t b0, uint32_t b1) {
    asm volatile(
        "mma.sync.aligned.m16n8k16.row.col.f32.f16.f16.f32 "
        "{%0,%1,%2,%3}, {%4,%5,%6,%7}, {%8,%9}, {%0,%1,%2,%3};"
        : "+f"(c[0]), "+f"(c[1]), "+f"(c[2]), "+f"(c[3])
        : "r"(a[0]), "r"(a[1]), "r"(a[2]), "r"(a[3]), "r"(b0), "r"(b1));
}
// pack two fp32 -> f16x2 (first arg -> low half)
__device__ __forceinline__ uint32_t pack_h(float lo, float hi) {
    uint32_t r;
    asm("cvt.rn.f16x2.f32 %0, %2, %1;" : "=r"(r) : "f"(lo), "f"(hi));
    return r;
}
// hardware exp2: single EX2 via MUFU (no log2e multiply)
__device__ __forceinline__ float hexp2(float x) {
    float r;
    asm("ex2.approx.f32 %0, %1;" : "=f"(r) : "f"(x));
    return r;
}

// ==================== fp32 x -> fp16 hi/lo ====================
__global__ __launch_bounds__(256) void conv_x_kernel(const float* __restrict__ src)
{
    int idx = (blockIdx.x * 256 + threadIdx.x) * 4;
    float4 v = *(const float4*)&src[idx];
    __half hx = __float2half(v.x), hy = __float2half(v.y);
    __half hz = __float2half(v.z), hw = __float2half(v.w);
    uint2 H, L;
    H.x = pack_h(v.x, v.y);
    H.y = pack_h(v.z, v.w);
    L.x = pack_h(v.x - __half2float(hx), v.y - __half2float(hy));
    L.y = pack_h(v.z - __half2float(hz), v.w - __half2float(hw));
    *(uint2*)&g_xh[idx] = H;
    *(uint2*)&g_xl[idx] = L;
}

// ==================== W transposes -> fp16 ====================
__global__ void conv_wT_kernel(const float* __restrict__ Wq, const float* __restrict__ Wk,
                               const float* __restrict__ Wv, const float* __restrict__ Wo,
                               const float* __restrict__ W1)
{
    __shared__ float t[32][33];
    int z = blockIdx.z;
    if (z == 4) {
        if (blockIdx.x >= 4) return;
        int n0 = blockIdx.x * 32, k0 = blockIdx.y * 32;   // n = p, k = d
        t[threadIdx.y][threadIdx.x] = W1[(size_t)(k0 + threadIdx.y) * PD + n0 + threadIdx.x];
        __syncthreads();
        float v = t[threadIdx.x][threadIdx.y];
        size_t o = (size_t)(n0 + threadIdx.y) * HID + k0 + threadIdx.x;
        __half h = __float2half(v);
        g_w1h[o] = h;
        g_w1l[o] = __float2half(v - __half2float(h));
        return;
    }
    const float* W = (z == 0) ? Wq : (z == 1) ? Wk : (z == 2) ? Wv : Wo;
    int n0 = blockIdx.x * 32, k0 = blockIdx.y * 32;
    t[threadIdx.y][threadIdx.x] = W[(size_t)(k0 + threadIdx.y) * HID + n0 + threadIdx.x];
    __syncthreads();
    float v = t[threadIdx.x][threadIdx.y];
    size_t o = ((size_t)z << 20) + (size_t)(n0 + threadIdx.y) * HID + k0 + threadIdx.x;
    g_wt[o] = __float2half(v);
}

// ==================== repo stage-1 GEMM: fp16 3-pass, pipelined ====================
#define RT       18432                 // 128 rows * 144 B
#define RG_BUF   (4 * RT)
#define RG_SMEM  (2 * RG_BUF)

__global__ __launch_bounds__(256) void repo_gemm_kernel()
{
    extern __shared__ __align__(128) char smem[];
    uint32_t sbase = smem_u32(smem);
    int tid = threadIdx.x, lane = tid & 31, wid = tid >> 5;
    int wm = wid & 3, wn = wid >> 2;

    int ks0 = blockIdx.x * 256;
    int m0  = blockIdx.y * 128;
    const __half* Ah = g_xh  + (size_t)m0 * HID + ks0;
    const __half* Al = g_xl  + (size_t)m0 * HID + ks0;
    const __half* Bh = g_w1h + ks0;
    const __half* Bl = g_w1l + ks0;
    const __half* bases[4] = {Ah, Al, Bh, Bl};

    float acc[2][8][4];
    #pragma unroll
    for (int i = 0; i < 2; i++)
        #pragma unroll
        for (int j = 0; j < 8; j++)
            #pragma unroll
            for (int q = 0; q < 4; q++) acc[i][j][q] = 0.f;

    int arow = lane & 15,  acg = lane >> 4;
    int brow = (lane & 7) + ((lane >> 4) << 3);
    int bcg  = (lane >> 3) & 1;

    #pragma unroll
    for (int it = 0; it < 16; it++) {
        int lin = it * 256 + tid;
        int tile = lin >> 10, idx = lin & 1023, r = idx >> 3, seg = idx & 7;
        cp_async16(sbase + tile * RT + r * 144 + seg * 16,
                   bases[tile] + (size_t)r * HID + seg * 8);
    }
    cp_commit();

    for (int c = 0; c < 4; c++) {
        if (c + 1 < 4) {
            int k0 = (c + 1) * 64;
            uint32_t sb = sbase + ((c + 1) & 1) * RG_BUF;
            #pragma unroll
            for (int it = 0; it < 16; it++) {
                int lin = it * 256 + tid;
                int tile = lin >> 10, idx = lin & 1023, r = idx >> 3, seg = idx & 7;
                cp_async16(sb + tile * RT + r * 144 + seg * 16,
                           bases[tile] + (size_t)r * HID + k0 + seg * 8);
            }
            cp_commit();
            asm volatile("cp.async.wait_group 1;" ::: "memory");
        } else {
            asm volatile("cp.async.wait_group 0;" ::: "memory");
        }
        __syncthreads();

        uint32_t sb = sbase + (c & 1) * RG_BUF;
        uint32_t sAh = sb, sAl = sb + RT, sBh = sb + 2 * RT, sBl = sb + 3 * RT;
        #pragma unroll
        for (int ks = 0; ks < 4; ks++) {
            uint32_t ah[2][4], al[2][4], bh[4][4], bl[4][4];
            #pragma unroll
            for (int i = 0; i < 2; i++) {
                ldsm_x4(ah[i], sAh + ((wm * 32 + i * 16 + arow) * 72 + ks * 16 + acg * 8) * 2);
                ldsm_x4(al[i], sAl + ((wm * 32 + i * 16 + arow) * 72 + ks * 16 + acg * 8) * 2);
            }
            #pragma unroll
            for (int j = 0; j < 4; j++) {
                ldsm_x4(bh[j], sBh + ((wn * 64 + j * 16 + brow) * 72 + ks * 16 + bcg * 8) * 2);
                ldsm_x4(bl[j], sBl + ((wn * 64 + j * 16 + brow) * 72 + ks * 16 + bcg * 8) * 2);
            }
            #pragma unroll
            for (int i = 0; i < 2; i++)
                #pragma unroll
                for (int j = 0; j < 8; j++) {
                    mma16816(acc[i][j], ah[i], bh[j >> 1][(j & 1) * 2], bh[j >> 1][(j & 1) * 2 + 1]);
                    mma16816(acc[i][j], ah[i], bl[j >> 1][(j & 1) * 2], bl[j >> 1][(j & 1) * 2 + 1]);
                    mma16816(acc[i][j], al[i], bh[j >> 1][(j & 1) * 2], bh[j >> 1][(j & 1) * 2 + 1]);
                }
        }
        __syncthreads();
    }

    float* Hs = g_H + (size_t)blockIdx.x * (BB * SS * PD);
    #pragma unroll
    for (int i = 0; i < 2; i++)
        #pragma unroll
        for (int j = 0; j < 8; j++) {
            int n = wn * 64 + j * 8 + (lane & 3) * 2;
            #pragma unroll
            for (int hf = 0; hf < 2; hf++) {
                int m = m0 + wm * 32 + i * 16 + (lane >> 2) + hf * 8;
                *(float2*)(Hs + (size_t)m * PD + n) =
                    make_float2(acc[i][j][hf * 2], acc[i][j][hf * 2 + 1]);
            }
        }
}

// ==================== repo finish ====================
__global__ __launch_bounds__(128) void repo_finish_kernel(
    const float* __restrict__ b1, const float* __restrict__ W2, const float* __restrict__ b2)
{
    int warp = threadIdx.x >> 5, lane = threadIdx.x & 31;
    int r = blockIdx.x * 4 + warp;
    float4 hv = make_float4(0.f, 0.f, 0.f, 0.f);
    #pragma unroll
    for (int sl = 0; sl < 4; sl++) {
        float4 t = *(const float4*)&g_H[(size_t)sl * (BB * SS * PD) + (size_t)r * PD + lane * 4];
        hv.x += t.x; hv.y += t.y; hv.z += t.z; hv.w += t.w;
    }
    float4 bb = *(const float4*)&b1[lane * 4];
    float4 w2 = *(const float4*)&W2[lane * 4];
    float vv[4] = {hv.x + bb.x, hv.y + bb.y, hv.z + bb.z, hv.w + bb.w};
    float ww[4] = {w2.x, w2.y, w2.z, w2.w};
    float sum = 0.f;
    #pragma unroll
    for (int q = 0; q < 4; q++) {
        float z = vv[q];
        float g = 0.5f * z * (1.f + tanhf(0.7978845608028654f * (z + 0.044715f * z * z * z)));
        sum += g * ww[q];
    }
    #pragma unroll
    for (int off = 16; off; off >>= 1) sum += __shfl_xor_sync(0xffffffffu, sum, off);
    if (lane == 0) {
        float raw = sum + b2[0];
        g_sp[r] = fmaxf(raw, 0.f) + log1pf(expf(-fabsf(raw)));
    }
}

// ==================== fp64 scan ====================
__global__ __launch_bounds__(1024) void scan_kernel()
{
    __shared__ double sc[1024];
    int b = blockIdx.x, t = threadIdx.x;
    float a0 = g_sp[b * SS + 2 * t];
    float a1 = g_sp[b * SS + 2 * t + 1];
    sc[t] = (double)a0 + (double)a1;
    __syncthreads();
    for (int off = 1; off < 1024; off <<= 1) {
        double v = (t >= off) ? sc[t - off] : 0.0;
        __syncthreads();
        sc[t] += v;
        __syncthreads();
    }
    double excl = (t == 0) ? 0.0 : sc[t - 1];
    g_posd[b * SS + 2 * t]     = excl + (double)a0;
    g_posd[b * SS + 2 * t + 1] = excl + (double)a0 + (double)a1;
}

// ==================== angles ====================
__global__ __launch_bounds__(256) void angles_kernel()
{
    int idx = blockIdx.x * 256 + threadIdx.x;
    int j = idx & 31, bs = idx >> 5;
    double f   = exp(((double)(-2 * j) / 64.0) * 9.210340371976184);
    double ang = g_posd[bs] * f;
    const double twopi = 6.283185307179586476925286766559;
    ang -= floor(ang * (1.0 / twopi)) * twopi;
    float af = (float)ang;
    g_cos[idx] = cosf(af);
    g_sin[idx] = sinf(af);
}

// ==================== mma.sync fp16 GEMM: 128x128 tile, BK=64, 256 threads, occ 2 ====
// MODE 0: A = g_xh, B = wt[z] (z = blockIdx.z in {0,1}); fused RoPE -> g_q / g_k
// MODE 2: A = g_xh, B = wt[2]; transpose -> g_vt (b,h,d,s)
// MODE 1: A = g_ah, B = wt[3]; row-major fp32 -> outp
#define TILE_B   18432
#define BUF_B    (2 * TILE_B)
#define SMEM_MM  (2 * BUF_B)

template<int MODE>
__global__ __launch_bounds__(256, 2) void mm_mma_kernel(float* __restrict__ outp)
{
    extern __shared__ __align__(128) char smem[];
    uint32_t sbase = smem_u32(smem);
    int tid = threadIdx.x;
    int lane = tid & 31, wid = tid >> 5;
    int wm = wid & 3, wn = wid >> 2;

    int n0 = blockIdx.x * 128, m0 = blockIdx.y * 128;
    int z  = (MODE == 0) ? (int)blockIdx.z : (MODE == 2 ? 2 : 3);
    const __half* A = ((MODE == 1) ? g_ah : g_xh) + (size_t)m0 * HID;
    const __half* B = g_wt + ((size_t)z << 20) + (size_t)n0 * HID;

    float acc[2][8][4];
    #pragma unroll
    for (int i = 0; i < 2; i++)
        #pragma unroll
        for (int j = 0; j < 8; j++)
            #pragma unroll
            for (int q = 0; q < 4; q++) acc[i][j][q] = 0.f;

    int arow = lane & 15,  acg = lane >> 4;
    int brow = (lane & 7) + ((lane >> 4) << 3);
    int bcg  = (lane >> 3) & 1;

    {
        const __half* bases[2] = {A, B};
        #pragma unroll
        for (int it = 0; it < 8; it++) {
            int lin = it * 256 + tid;
            int tile = lin >> 10, idx = lin & 1023, r = idx >> 3, seg = idx & 7;
            cp_async16(sbase + tile * TILE_B + r * 144 + seg * 16,
                       bases[tile] + (size_t)r * HID + seg * 8);
        }
        cp_commit();
    }

    for (int c = 0; c < 16; c++) {
        if (c + 1 < 16) {
            int k0 = (c + 1) * 64;
            uint32_t sb = sbase + ((c + 1) & 1) * BUF_B;
            const __half* bases[2] = {A, B};
            #pragma unroll
            for (int it = 0; it < 8; it++) {
                int lin = it * 256 + tid;
                int tile = lin >> 10, idx = lin & 1023, r = idx >> 3, seg = idx & 7;
                cp_async16(sb + tile * TILE_B + r * 144 + seg * 16,
                           bases[tile] + (size_t)r * HID + k0 + seg * 8);
            }
            cp_commit();
            asm volatile("cp.async.wait_group 1;" ::: "memory");
        } else {
            asm volatile("cp.async.wait_group 0;" ::: "memory");
        }
        __syncthreads();

        uint32_t sb = sbase + (c & 1) * BUF_B;
        uint32_t sA = sb, sB = sb + TILE_B;

        #pragma unroll
        for (int ks = 0; ks < 4; ks++) {
            uint32_t a[2][4], bh[4][4];
            #pragma unroll
            for (int i = 0; i < 2; i++)
                ldsm_x4(a[i], sA + ((wm * 32 + i * 16 + arow) * 72 + ks * 16 + acg * 8) * 2);
            #pragma unroll
            for (int j = 0; j < 4; j++)
                ldsm_x4(bh[j], sB + ((wn * 64 + j * 16 + brow) * 72 + ks * 16 + bcg * 8) * 2);
            #pragma unroll
            for (int i = 0; i < 2; i++)
                #pragma unroll
                for (int j = 0; j < 8; j++)
                    mma16816(acc[i][j], a[i], bh[j >> 1][(j & 1) * 2], bh[j >> 1][(j & 1) * 2 + 1]);
        }
        __syncthreads();
    }

    // ---- epilogue ----
    if (MODE == 1) {
        #pragma unroll
        for (int i = 0; i < 2; i++)
            #pragma unroll
            for (int j = 0; j < 8; j++) {
                int n = n0 + wn * 64 + j * 8 + (lane & 3) * 2;
                #pragma unroll
                for (int hf = 0; hf < 2; hf++) {
                    int m = m0 + wm * 32 + i * 16 + (lane >> 2) + hf * 8;
                    *(float2*)(outp + (size_t)m * HID + n) =
                        make_float2(acc[i][j][hf * 2], acc[i][j][hf * 2 + 1]);
                }
            }
        return;
    }

    int h = (n0 + wn * 64) >> 6;
    if (MODE == 2) {
        #pragma unroll
        for (int i = 0; i < 2; i++)
            #pragma unroll
            for (int hf = 0; hf < 2; hf++) {
                int m = m0 + wm * 32 + i * 16 + (lane >> 2) + hf * 8;
                int b = m >> 11, s = m & 2047;
                size_t basev = ((size_t)(b * HH + h)) * DD * SS + s;
                #pragma unroll
                for (int j = 0; j < 8; j++) {
                    int d = j * 8 + (lane & 3) * 2;
                    g_vt[basev + (size_t)d * SS]       = __float2half(acc[i][j][hf * 2]);
                    g_vt[basev + (size_t)(d + 1) * SS] = __float2half(acc[i][j][hf * 2 + 1]);
                }
            }
    } else {
        __half* dst = (z == 0) ? g_q : g_k;
        // Q scale folds 1/sqrt(64) * log2(e) so flash softmax works in exp2 domain
        float qscale = (z == 0) ? 0.18033688011112042f : 1.0f;
        #pragma unroll
        for (int i = 0; i < 2; i++)
            #pragma unroll
            for (int hf = 0; hf < 2; hf++) {
                int m = m0 + wm * 32 + i * 16 + (lane >> 2) + hf * 8;
                int b = m >> 11, s = m & 2047;
                size_t baseo = ((size_t)((b * HH + h) * SS + s)) * DD;
                int cbase = (b * SS + s) * 32;
                #pragma unroll
                for (int j = 0; j < 4; j++) {
                    int d = j * 8 + (lane & 3) * 2;
                    float c0 = g_cos[cbase + d],     sn0 = g_sin[cbase + d];
                    float c1 = g_cos[cbase + d + 1], sn1 = g_sin[cbase + d + 1];
                    float t1a = acc[i][j][hf * 2],     t1b = acc[i][j][hf * 2 + 1];
                    float t2a = acc[i][j + 4][hf * 2], t2b = acc[i][j + 4][hf * 2 + 1];
                    float ra  = qscale * (t1a * c0 - t2a * sn0);
                    float rb  = qscale * (t1b * c1 - t2b * sn1);
                    float r2a = qscale * (t1a * sn0 + t2a * c0);
                    float r2b = qscale * (t1b * sn1 + t2b * c1);
                    *(uint32_t*)&dst[baseo + d]      = pack_h(ra, rb);
                    *(uint32_t*)&dst[baseo + d + 32] = pack_h(r2a, r2b);
                }
            }
    }
}

// ==================== Flash attention: BQ=128, BKV=64, exp2 (MUFU) softmax ====================
#define FT     9216
#define FBUF   (2 * FT)
#define SMEM_F (2 * FBUF)

__global__ __launch_bounds__(256, 2) void flash_mma_kernel()
{
    extern __shared__ __align__(128) char fsm[];
    uint32_t sbase = smem_u32(fsm);
    int tid = threadIdx.x, lane = tid & 31, w = tid >> 5;
    int qt = blockIdx.x, bh = blockIdx.y;
    int b = bh >> 4, h = bh & 15;

    const __half* Q  = g_q  + ((size_t)bh * SS + qt * 128) * DD;
    const __half* K  = g_k  + (size_t)bh * SS * DD;
    const __half* Vt = g_vt + (size_t)bh * DD * SS;

    int arow = lane & 15, acg = lane >> 4;
    int brow = (lane & 7) + ((lane >> 4) << 3), bcg = (lane >> 3) & 1;

    #pragma unroll
    for (int it = 0; it < 4; it++) {
        int lin = it * 256 + tid;
        int r = lin >> 3, seg = lin & 7;
        cp_async16(sbase + r * 144 + seg * 16, Q + (size_t)r * DD + seg * 8);
    }
    cp_commit();
    asm volatile("cp.async.wait_group 0;" ::: "memory");
    __syncthreads();
    uint32_t aq[4][4];
    #pragma unroll
    for (int kb = 0; kb < 4; kb++)
        ldsm_x4(aq[kb], sbase + ((w * 16 + arow) * 72 + kb * 16 + acg * 8) * 2);
    __syncthreads();

    float s[8][4], o[8][4];
    #pragma unroll
    for (int j = 0; j < 8; j++)
        #pragma unroll
        for (int q = 0; q < 4; q++) o[j][q] = 0.f;
    float m0 = -1e30f, m1 = -1e30f, l0 = 0.f, l1 = 0.f;

    {
        #pragma unroll
        for (int it = 0; it < 4; it++) {
            int lin = it * 256 + tid;
            int tile = lin >> 9, idx = lin & 511;
            int r = idx >> 3, seg = idx & 7;
            const __half* src = (tile == 0) ? K  + (size_t)r * DD + seg * 8
                                            : Vt + (size_t)r * SS + seg * 8;
            cp_async16(sbase + tile * FT + r * 144 + seg * 16, src);
        }
        cp_commit();
    }

    for (int c = 0; c < 32; c++) {
        if (c + 1 < 32) {
            int kbase = (c + 1) * 64;
            uint32_t sb = sbase + ((c + 1) & 1) * FBUF;
            #pragma unroll
            for (int it = 0; it < 4; it++) {
                int lin = it * 256 + tid;
                int tile = lin >> 9, idx = lin & 511;
                int r = idx >> 3, seg = idx & 7;
                const __half* src = (tile == 0) ? K  + (size_t)(kbase + r) * DD + seg * 8
                                                : Vt + (size_t)r * SS + kbase + seg * 8;
                cp_async16(sb + tile * FT + r * 144 + seg * 16, src);
            }
            cp_commit();
            asm volatile("cp.async.wait_group 1;" ::: "memory");
        } else {
            asm volatile("cp.async.wait_group 0;" ::: "memory");
        }
        __syncthreads();

        uint32_t sb = sbase + (c & 1) * FBUF;

        #pragma unroll
        for (int j = 0; j < 8; j++) { s[j][0] = s[j][1] = s[j][2] = s[j][3] = 0.f; }
        #pragma unroll
        for (int kb = 0; kb < 4; kb++) {
            uint32_t kh[4][4];
            #pragma unroll
            for (int j = 0; j < 4; j++)
                ldsm_x4(kh[j], sb + ((j * 16 + brow) * 72 + kb * 16 + bcg * 8) * 2);
            #pragma unroll
            for (int j = 0; j < 8; j++)
                mma16816(s[j], aq[kb], kh[j >> 1][(j & 1) * 2], kh[j >> 1][(j & 1) * 2 + 1]);
        }

        // ---- online softmax, log2 domain, hardware EX2 ----
        float mx0 = s[0][0], mx1 = s[0][2];
        #pragma unroll
        for (int j = 0; j < 8; j++) {
            mx0 = fmaxf(mx0, fmaxf(s[j][0], s[j][1]));
            mx1 = fmaxf(mx1, fmaxf(s[j][2], s[j][3]));
        }
        mx0 = fmaxf(mx0, __shfl_xor_sync(0xffffffffu, mx0, 1));
        mx0 = fmaxf(mx0, __shfl_xor_sync(0xffffffffu, mx0, 2));
        mx1 = fmaxf(mx1, __shfl_xor_sync(0xffffffffu, mx1, 1));
        mx1 = fmaxf(mx1, __shfl_xor_sync(0xffffffffu, mx1, 2));
        float mn0 = fmaxf(m0, mx0), mn1 = fmaxf(m1, mx1);
        float al0 = hexp2(m0 - mn0), al1 = hexp2(m1 - mn1);
        m0 = mn0; m1 = mn1;
        float sum0 = 0.f, sum1 = 0.f;
        #pragma unroll
        for (int j = 0; j < 8; j++) {
            s[j][0] = hexp2(s[j][0] - mn0);
            s[j][1] = hexp2(s[j][1] - mn0);
            s[j][2] = hexp2(s[j][2] - mn1);
            s[j][3] = hexp2(s[j][3] - mn1);
            sum0 += s[j][0] + s[j][1];
            sum1 += s[j][2] + s[j][3];
        }
        sum0 += __shfl_xor_sync(0xffffffffu, sum0, 1);
        sum0 += __shfl_xor_sync(0xffffffffu, sum0, 2);
        sum1 += __shfl_xor_sync(0xffffffffu, sum1, 1);
        sum1 += __shfl_xor_sync(0xffffffffu, sum1, 2);
        l0 = l0 * al0 + sum0;
        l1 = l1 * al1 + sum1;
        #pragma unroll
        for (int j = 0; j < 8; j++) {
            o[j][0] *= al0; o[j][1] *= al0; o[j][2] *= al1; o[j][3] *= al1;
        }

        #pragma unroll
        for (int kb = 0; kb < 4; kb++) {
            uint32_t ph[4];
            ph[0] = pack_h(s[2 * kb][0],     s[2 * kb][1]);
            ph[1] = pack_h(s[2 * kb][2],     s[2 * kb][3]);
            ph[2] = pack_h(s[2 * kb + 1][0], s[2 * kb + 1][1]);
            ph[3] = pack_h(s[2 * kb + 1][2], s[2 * kb + 1][3]);

            uint32_t vh[4][4];
            #pragma unroll
            for (int j = 0; j < 4; j++)
                ldsm_x4(vh[j], sb + FT + ((j * 16 + brow) * 72 + kb * 16 + bcg * 8) * 2);
            #pragma unroll
            for (int j = 0; j < 8; j++)
                mma16816(o[j], ph, vh[j >> 1][(j & 1) * 2], vh[j >> 1][(j & 1) * 2 + 1]);
        }
        __syncthreads();
    }

    float i0 = 1.f / l0, i1 = 1.f / l1;
    int r0 = qt * 128 + w * 16 + (lane >> 2);
    #pragma unroll
    for (int j = 0; j < 8; j++) {
        int n = h * 64 + j * 8 + (lane & 3) * 2;
        size_t o0 = ((size_t)(b * SS) + r0) * HID + n;
        size_t o1 = o0 + 8 * HID;
        *(uint32_t*)&g_ah[o0] = pack_h(o[j][0] * i0, o[j][1] * i0);
        *(uint32_t*)&g_ah[o1] = pack_h(o[j][2] * i1, o[j][3] * i1);
    }
}

// ==================== launch (resource-disjoint overlap only) ====================
extern "C" void kernel_launch(void* const* d_in, const int* in_sizes, int n_in,
                              void* d_out, int out_size)
{
    const float* x  = (const float*)d_in[0];
    const float* Wq = (const float*)d_in[1];
    const float* Wk = (const float*)d_in[2];
    const float* Wv = (const float*)d_in[3];
    const float* Wo = (const float*)d_in[4];
    const float* W1 = (const float*)d_in[5];
    const float* b1 = (const float*)d_in[6];
    const float* W2 = (const float*)d_in[7];
    const float* b2 = (const float*)d_in[8];
    float* out = (float*)d_out;

    cudaFuncSetAttribute(mm_mma_kernel<0>, cudaFuncAttributeMaxDynamicSharedMemorySize, SMEM_MM);
    cudaFuncSetAttribute(mm_mma_kernel<1>, cudaFuncAttributeMaxDynamicSharedMemorySize, SMEM_MM);
    cudaFuncSetAttribute(mm_mma_kernel<2>, cudaFuncAttributeMaxDynamicSharedMemorySize, SMEM_MM);
    cudaFuncSetAttribute(flash_mma_kernel, cudaFuncAttributeMaxDynamicSharedMemorySize, SMEM_F);
    cudaFuncSetAttribute(repo_gemm_kernel, cudaFuncAttributeMaxDynamicSharedMemorySize, RG_SMEM);

    // Per-call stream/events, intentionally leaked (destroying capture-participating
    // resources can invalidate the graph; kernel_launch runs only a few times).
    cudaStream_t s2;
    cudaStreamCreateWithFlags(&s2, cudaStreamNonBlocking);
    cudaEvent_t e0, e1, e2, e3;
    cudaEventCreateWithFlags(&e0, cudaEventDisableTiming);
    cudaEventCreateWithFlags(&e1, cudaEventDisableTiming);
    cudaEventCreateWithFlags(&e2, cudaEventDisableTiming);
    cudaEventCreateWithFlags(&e3, cudaEventDisableTiming);

    // fork 1: conv_x (s2, memory-bound) || conv_wT (main, memory-bound)
    cudaEventRecord(e0, 0);
    cudaStreamWaitEvent(s2, e0, 0);
    conv_x_kernel<<<4096, 256, 0, s2>>>(x);
    cudaEventRecord(e1, s2);
    conv_wT_kernel<<<dim3(32, 32, 5), dim3(32, 32)>>>(Wq, Wk, Wv, Wo, W1);
    cudaStreamWaitEvent(0, e1, 0);

    // serial: repo chain through repo_finish (tensor-bound; no overlap with GEMMs)
    repo_gemm_kernel<<<dim3(4, 32), 256, RG_SMEM>>>();
    repo_finish_kernel<<<1024, 128>>>(b1, W2, b2);

    // fork 2: scan+angles (s2, tiny ALU/MUFU/mem) || V-GEMM (main, tensor-bound)
    cudaEventRecord(e2, 0);
    cudaStreamWaitEvent(s2, e2, 0);
    scan_kernel<<<2, 1024, 0, s2>>>();
    angles_kernel<<<512, 256, 0, s2>>>();
    cudaEventRecord(e3, s2);

    mm_mma_kernel<2><<<dim3(8, 32), 256, SMEM_MM>>>(nullptr);     // V projection (no RoPE dep)
    cudaStreamWaitEvent(0, e3, 0);                                // join: angles ready

    mm_mma_kernel<0><<<dim3(8, 32, 2), 256, SMEM_MM>>>(nullptr);  // Q/K with fused RoPE
    flash_mma_kernel<<<dim3(16, 32), 256, SMEM_F>>>();
    mm_mma_kernel<1><<<dim3(8, 32), 256, SMEM_MM>>>(out);
}

// round 17
// speedup vs baseline: 1.1668x; 1.0001x over previous
#include <cuda_runtime.h>
#include <cuda_fp16.h>
#include <math.h>
#include <stdint.h>

#define BB   2
#define SS   2048
#define HH   16
#define DD   64
#define HID  1024
#define PD   128

// ---------------- scratch (device globals — no allocation allowed) ----------------
__device__ float  g_sp[BB*SS];
__device__ double g_posd[BB*SS];
__device__ __align__(256) float g_cos[BB*SS*32];
__device__ __align__(256) float g_sin[BB*SS*32];
// fp16 operands
__device__ __align__(256) __half g_xh[BB*SS*HID];        // x fp16 (hi)
__device__ __align__(256) __half g_xl[BB*SS*HID];        // x fp16 (lo residual)
__device__ __align__(256) __half g_ah[BB*SS*HID];        // attention out fp16
__device__ __align__(256) __half g_wt[4*HID*HID];        // W^T (n,k) fp16, z = q,k,v,o
__device__ __align__(256) __half g_w1h[PD*HID];          // W1^T (p,d) fp16 hi
__device__ __align__(256) __half g_w1l[PD*HID];          // W1^T (p,d) fp16 lo
__device__ __align__(256) float  g_H[4*BB*SS*PD];        // repo H partials, 4 k-slices
__device__ __align__(256) __half g_q[BB*HH*SS*DD];       // (b,h,s,d), RoPE'd, scaled 0.125*log2e
__device__ __align__(256) __half g_k[BB*HH*SS*DD];       // (b,h,s,d), RoPE'd
__device__ __align__(256) __half g_vt[BB*HH*DD*SS];      // (b,h,d,s)  V^T

// ==================== helpers ====================
__device__ __forceinline__ uint32_t smem_u32(const void* p) {
    uint32_t a;
    asm("{ .reg .u64 t; cvta.to.shared.u64 t, %1; cvt.u32.u64 %0, t; }" : "=r"(a) : "l"(p));
    return a;
}
__device__ __forceinline__ void cp_async16(uint32_t dst, const void* src) {
    asm volatile("cp.async.cg.shared.global [%0], [%1], 16;" :: "r"(dst), "l"(src));
}
__device__ __forceinline__ void cp_commit() {
    asm volatile("cp.async.commit_group;" ::: "memory");
}
__device__ __forceinline__ void ldsm_x4(uint32_t* r, uint32_t addr) {
    asm volatile("ldmatrix.sync.aligned.m8n8.x4.shared.b16 {%0,%1,%2,%3}, [%4];"
                 : "=r"(r[0]), "=r"(r[1]), "=r"(r[2]), "=r"(r[3]) : "r"(addr));
}
__device__ __forceinline__ void mma16816(float* c, const uint32_t* a, uint32_t b0, uint32_t b1) {
    asm volatile(
        "mma.sync.aligned.m16n8k16.row.col.f32.f16.f16.f32 "
        "{%0,%1,%2,%3}, {%4,%5,%6,%7}, {%8,%9}, {%0,%1,%2,%3};"
        : "+f"(c[0]), "+f"(c[1]), "+f"(c[2]), "+f"(c[3])
        : "r"(a[0]), "r"(a[1]), "r"(a[2]), "r"(a[3]), "r"(b0), "r"(b1));
}
// pack two fp32 -> f16x2 (first arg -> low half)
__device__ __forceinline__ uint32_t pack_h(float lo, float hi) {
    uint32_t r;
    asm("cvt.rn.f16x2.f32 %0, %2, %1;" : "=r"(r) : "f"(lo), "f"(hi));
    return r;
}
// hardware exp2: single EX2 via MUFU (no log2e multiply)
__device__ __forceinline__ float hexp2(float x) {
    float r;
    asm("ex2.approx.f32 %0, %1;" : "=f"(r) : "f"(x));
    return r;
}

// ==================== fp32 x -> fp16 hi/lo ====================
__global__ __launch_bounds__(256) void conv_x_kernel(const float* __restrict__ src)
{
    int idx = (blockIdx.x * 256 + threadIdx.x) * 4;
    float4 v = *(const float4*)&src[idx];
    __half hx = __float2half(v.x), hy = __float2half(v.y);
    __half hz = __float2half(v.z), hw = __float2half(v.w);
    uint2 H, L;
    H.x = pack_h(v.x, v.y);
    H.y = pack_h(v.z, v.w);
    L.x = pack_h(v.x - __half2float(hx), v.y - __half2float(hy));
    L.y = pack_h(v.z - __half2float(hz), v.w - __half2float(hw));
    *(uint2*)&g_xh[idx] = H;
    *(uint2*)&g_xl[idx] = L;
}

// ==================== W transposes -> fp16 ====================
__global__ void conv_wT_kernel(const float* __restrict__ Wq, const float* __restrict__ Wk,
                               const float* __restrict__ Wv, const float* __restrict__ Wo,
                               const float* __restrict__ W1)
{
    __shared__ float t[32][33];
    int z = blockIdx.z;
    if (z == 4) {
        if (blockIdx.x >= 4) return;
        int n0 = blockIdx.x * 32, k0 = blockIdx.y * 32;   // n = p, k = d
        t[threadIdx.y][threadIdx.x] = W1[(size_t)(k0 + threadIdx.y) * PD + n0 + threadIdx.x];
        __syncthreads();
        float v = t[threadIdx.x][threadIdx.y];
        size_t o = (size_t)(n0 + threadIdx.y) * HID + k0 + threadIdx.x;
        __half h = __float2half(v);
        g_w1h[o] = h;
        g_w1l[o] = __float2half(v - __half2float(h));
        return;
    }
    const float* W = (z == 0) ? Wq : (z == 1) ? Wk : (z == 2) ? Wv : Wo;
    int n0 = blockIdx.x * 32, k0 = blockIdx.y * 32;
    t[threadIdx.y][threadIdx.x] = W[(size_t)(k0 + threadIdx.y) * HID + n0 + threadIdx.x];
    __syncthreads();
    float v = t[threadIdx.x][threadIdx.y];
    size_t o = ((size_t)z << 20) + (size_t)(n0 + threadIdx.y) * HID + k0 + threadIdx.x;
    g_wt[o] = __float2half(v);
}

// ==================== repo stage-1 GEMM: fp16 3-pass, pipelined ====================
#define RT       18432                 // 128 rows * 144 B
#define RG_BUF   (4 * RT)
#define RG_SMEM  (2 * RG_BUF)

__global__ __launch_bounds__(256) void repo_gemm_kernel()
{
    extern __shared__ __align__(128) char smem[];
    uint32_t sbase = smem_u32(smem);
    int tid = threadIdx.x, lane = tid & 31, wid = tid >> 5;
    int wm = wid & 3, wn = wid >> 2;

    int ks0 = blockIdx.x * 256;
    int m0  = blockIdx.y * 128;
    const __half* Ah = g_xh  + (size_t)m0 * HID + ks0;
    const __half* Al = g_xl  + (size_t)m0 * HID + ks0;
    const __half* Bh = g_w1h + ks0;
    const __half* Bl = g_w1l + ks0;
    const __half* bases[4] = {Ah, Al, Bh, Bl};

    float acc[2][8][4];
    #pragma unroll
    for (int i = 0; i < 2; i++)
        #pragma unroll
        for (int j = 0; j < 8; j++)
            #pragma unroll
            for (int q = 0; q < 4; q++) acc[i][j][q] = 0.f;

    int arow = lane & 15,  acg = lane >> 4;
    int brow = (lane & 7) + ((lane >> 4) << 3);
    int bcg  = (lane >> 3) & 1;

    #pragma unroll
    for (int it = 0; it < 16; it++) {
        int lin = it * 256 + tid;
        int tile = lin >> 10, idx = lin & 1023, r = idx >> 3, seg = idx & 7;
        cp_async16(sbase + tile * RT + r * 144 + seg * 16,
                   bases[tile] + (size_t)r * HID + seg * 8);
    }
    cp_commit();

    for (int c = 0; c < 4; c++) {
        if (c + 1 < 4) {
            int k0 = (c + 1) * 64;
            uint32_t sb = sbase + ((c + 1) & 1) * RG_BUF;
            #pragma unroll
            for (int it = 0; it < 16; it++) {
                int lin = it * 256 + tid;
                int tile = lin >> 10, idx = lin & 1023, r = idx >> 3, seg = idx & 7;
                cp_async16(sb + tile * RT + r * 144 + seg * 16,
                           bases[tile] + (size_t)r * HID + k0 + seg * 8);
            }
            cp_commit();
            asm volatile("cp.async.wait_group 1;" ::: "memory");
        } else {
            asm volatile("cp.async.wait_group 0;" ::: "memory");
        }
        __syncthreads();

        uint32_t sb = sbase + (c & 1) * RG_BUF;
        uint32_t sAh = sb, sAl = sb + RT, sBh = sb + 2 * RT, sBl = sb + 3 * RT;
        #pragma unroll
        for (int ks = 0; ks < 4; ks++) {
            uint32_t ah[2][4], al[2][4], bh[4][4], bl[4][4];
            #pragma unroll
            for (int i = 0; i < 2; i++) {
                ldsm_x4(ah[i], sAh + ((wm * 32 + i * 16 + arow) * 72 + ks * 16 + acg * 8) * 2);
                ldsm_x4(al[i], sAl + ((wm * 32 + i * 16 + arow) * 72 + ks * 16 + acg * 8) * 2);
            }
            #pragma unroll
            for (int j = 0; j < 4; j++) {
                ldsm_x4(bh[j], sBh + ((wn * 64 + j * 16 + brow) * 72 + ks * 16 + bcg * 8) * 2);
                ldsm_x4(bl[j], sBl + ((wn * 64 + j * 16 + brow) * 72 + ks * 16 + bcg * 8) * 2);
            }
            #pragma unroll
            for (int i = 0; i < 2; i++)
                #pragma unroll
                for (int j = 0; j < 8; j++) {
                    mma16816(acc[i][j], ah[i], bh[j >> 1][(j & 1) * 2], bh[j >> 1][(j & 1) * 2 + 1]);
                    mma16816(acc[i][j], ah[i], bl[j >> 1][(j & 1) * 2], bl[j >> 1][(j & 1) * 2 + 1]);
                    mma16816(acc[i][j], al[i], bh[j >> 1][(j & 1) * 2], bh[j >> 1][(j & 1) * 2 + 1]);
                }
        }
        __syncthreads();
    }

    float* Hs = g_H + (size_t)blockIdx.x * (BB * SS * PD);
    #pragma unroll
    for (int i = 0; i < 2; i++)
        #pragma unroll
        for (int j = 0; j < 8; j++) {
            int n = wn * 64 + j * 8 + (lane & 3) * 2;
            #pragma unroll
            for (int hf = 0; hf < 2; hf++) {
                int m = m0 + wm * 32 + i * 16 + (lane >> 2) + hf * 8;
                *(float2*)(Hs + (size_t)m * PD + n) =
                    make_float2(acc[i][j][hf * 2], acc[i][j][hf * 2 + 1]);
            }
        }
}

// ==================== repo finish ====================
__global__ __launch_bounds__(128) void repo_finish_kernel(
    const float* __restrict__ b1, const float* __restrict__ W2, const float* __restrict__ b2)
{
    int warp = threadIdx.x >> 5, lane = threadIdx.x & 31;
    int r = blockIdx.x * 4 + warp;
    float4 hv = make_float4(0.f, 0.f, 0.f, 0.f);
    #pragma unroll
    for (int sl = 0; sl < 4; sl++) {
        float4 t = *(const float4*)&g_H[(size_t)sl * (BB * SS * PD) + (size_t)r * PD + lane * 4];
        hv.x += t.x; hv.y += t.y; hv.z += t.z; hv.w += t.w;
    }
    float4 bb = *(const float4*)&b1[lane * 4];
    float4 w2 = *(const float4*)&W2[lane * 4];
    float vv[4] = {hv.x + bb.x, hv.y + bb.y, hv.z + bb.z, hv.w + bb.w};
    float ww[4] = {w2.x, w2.y, w2.z, w2.w};
    float sum = 0.f;
    #pragma unroll
    for (int q = 0; q < 4; q++) {
        float z = vv[q];
        float g = 0.5f * z * (1.f + tanhf(0.7978845608028654f * (z + 0.044715f * z * z * z)));
        sum += g * ww[q];
    }
    #pragma unroll
    for (int off = 16; off; off >>= 1) sum += __shfl_xor_sync(0xffffffffu, sum, off);
    if (lane == 0) {
        float raw = sum + b2[0];
        g_sp[r] = fmaxf(raw, 0.f) + log1pf(expf(-fabsf(raw)));
    }
}

// ==================== fp64 scan ====================
__global__ __launch_bounds__(1024) void scan_kernel()
{
    __shared__ double sc[1024];
    int b = blockIdx.x, t = threadIdx.x;
    float a0 = g_sp[b * SS + 2 * t];
    float a1 = g_sp[b * SS + 2 * t + 1];
    sc[t] = (double)a0 + (double)a1;
    __syncthreads();
    for (int off = 1; off < 1024; off <<= 1) {
        double v = (t >= off) ? sc[t - off] : 0.0;
        __syncthreads();
        sc[t] += v;
        __syncthreads();
    }
    double excl = (t == 0) ? 0.0 : sc[t - 1];
    g_posd[b * SS + 2 * t]     = excl + (double)a0;
    g_posd[b * SS + 2 * t + 1] = excl + (double)a0 + (double)a1;
}

// ==================== angles ====================
__global__ __launch_bounds__(256) void angles_kernel()
{
    int idx = blockIdx.x * 256 + threadIdx.x;
    int j = idx & 31, bs = idx >> 5;
    double f   = exp(((double)(-2 * j) / 64.0) * 9.210340371976184);
    double ang = g_posd[bs] * f;
    const double twopi = 6.283185307179586476925286766559;
    ang -= floor(ang * (1.0 / twopi)) * twopi;
    float af = (float)ang;
    g_cos[idx] = cosf(af);
    g_sin[idx] = sinf(af);
}

// ==================== mma.sync fp16 GEMM: 128x128 tile, BK=64, 256 threads, occ 2 ====
// MODE 0: A = g_xh, B = wt[z] (z = blockIdx.z in {0,1}); fused RoPE -> g_q / g_k
// MODE 2: A = g_xh, B = wt[2]; transpose -> g_vt (b,h,d,s)
// MODE 1: A = g_ah, B = wt[3]; row-major fp32 -> outp
#define TILE_B   18432
#define BUF_B    (2 * TILE_B)
#define SMEM_MM  (2 * BUF_B)

template<int MODE>
__global__ __launch_bounds__(256, 2) void mm_mma_kernel(float* __restrict__ outp)
{
    extern __shared__ __align__(128) char smem[];
    uint32_t sbase = smem_u32(smem);
    int tid = threadIdx.x;
    int lane = tid & 31, wid = tid >> 5;
    int wm = wid & 3, wn = wid >> 2;

    int n0 = blockIdx.x * 128, m0 = blockIdx.y * 128;
    int z  = (MODE == 0) ? (int)blockIdx.z : (MODE == 2 ? 2 : 3);
    const __half* A = ((MODE == 1) ? g_ah : g_xh) + (size_t)m0 * HID;
    const __half* B = g_wt + ((size_t)z << 20) + (size_t)n0 * HID;

    float acc[2][8][4];
    #pragma unroll
    for (int i = 0; i < 2; i++)
        #pragma unroll
        for (int j = 0; j < 8; j++)
            #pragma unroll
            for (int q = 0; q < 4; q++) acc[i][j][q] = 0.f;

    int arow = lane & 15,  acg = lane >> 4;
    int brow = (lane & 7) + ((lane >> 4) << 3);
    int bcg  = (lane >> 3) & 1;

    {
        const __half* bases[2] = {A, B};
        #pragma unroll
        for (int it = 0; it < 8; it++) {
            int lin = it * 256 + tid;
            int tile = lin >> 10, idx = lin & 1023, r = idx >> 3, seg = idx & 7;
            cp_async16(sbase + tile * TILE_B + r * 144 + seg * 16,
                       bases[tile] + (size_t)r * HID + seg * 8);
        }
        cp_commit();
    }

    for (int c = 0; c < 16; c++) {
        if (c + 1 < 16) {
            int k0 = (c + 1) * 64;
            uint32_t sb = sbase + ((c + 1) & 1) * BUF_B;
            const __half* bases[2] = {A, B};
            #pragma unroll
            for (int it = 0; it < 8; it++) {
                int lin = it * 256 + tid;
                int tile = lin >> 10, idx = lin & 1023, r = idx >> 3, seg = idx & 7;
                cp_async16(sb + tile * TILE_B + r * 144 + seg * 16,
                           bases[tile] + (size_t)r * HID + k0 + seg * 8);
            }
            cp_commit();
            asm volatile("cp.async.wait_group 1;" ::: "memory");
        } else {
            asm volatile("cp.async.wait_group 0;" ::: "memory");
        }
        __syncthreads();

        uint32_t sb = sbase + (c & 1) * BUF_B;
        uint32_t sA = sb, sB = sb + TILE_B;

        #pragma unroll
        for (int ks = 0; ks < 4; ks++) {
            uint32_t a[2][4], bh[4][4];
            #pragma unroll
            for (int i = 0; i < 2; i++)
                ldsm_x4(a[i], sA + ((wm * 32 + i * 16 + arow) * 72 + ks * 16 + acg * 8) * 2);
            #pragma unroll
            for (int j = 0; j < 4; j++)
                ldsm_x4(bh[j], sB + ((wn * 64 + j * 16 + brow) * 72 + ks * 16 + bcg * 8) * 2);
            #pragma unroll
            for (int i = 0; i < 2; i++)
                #pragma unroll
                for (int j = 0; j < 8; j++)
                    mma16816(acc[i][j], a[i], bh[j >> 1][(j & 1) * 2], bh[j >> 1][(j & 1) * 2 + 1]);
        }
        __syncthreads();
    }

    // ---- epilogue ----
    if (MODE == 1) {
        #pragma unroll
        for (int i = 0; i < 2; i++)
            #pragma unroll
            for (int j = 0; j < 8; j++) {
                int n = n0 + wn * 64 + j * 8 + (lane & 3) * 2;
                #pragma unroll
                for (int hf = 0; hf < 2; hf++) {
                    int m = m0 + wm * 32 + i * 16 + (lane >> 2) + hf * 8;
                    *(float2*)(outp + (size_t)m * HID + n) =
                        make_float2(acc[i][j][hf * 2], acc[i][j][hf * 2 + 1]);
                }
            }
        return;
    }

    int h = (n0 + wn * 64) >> 6;
    if (MODE == 2) {
        #pragma unroll
        for (int i = 0; i < 2; i++)
            #pragma unroll
            for (int hf = 0; hf < 2; hf++) {
                int m = m0 + wm * 32 + i * 16 + (lane >> 2) + hf * 8;
                int b = m >> 11, s = m & 2047;
                size_t basev = ((size_t)(b * HH + h)) * DD * SS + s;
                #pragma unroll
                for (int j = 0; j < 8; j++) {
                    int d = j * 8 + (lane & 3) * 2;
                    g_vt[basev + (size_t)d * SS]       = __float2half(acc[i][j][hf * 2]);
                    g_vt[basev + (size_t)(d + 1) * SS] = __float2half(acc[i][j][hf * 2 + 1]);
                }
            }
    } else {
        __half* dst = (z == 0) ? g_q : g_k;
        // Q scale folds 1/sqrt(64) * log2(e) so flash softmax works in exp2 domain
        float qscale = (z == 0) ? 0.18033688011112042f : 1.0f;
        #pragma unroll
        for (int i = 0; i < 2; i++)
            #pragma unroll
            for (int hf = 0; hf < 2; hf++) {
                int m = m0 + wm * 32 + i * 16 + (lane >> 2) + hf * 8;
                int b = m >> 11, s = m & 2047;
                size_t baseo = ((size_t)((b * HH + h) * SS + s)) * DD;
                int cbase = (b * SS + s) * 32;
                #pragma unroll
                for (int j = 0; j < 4; j++) {
                    int d = j * 8 + (lane & 3) * 2;
                    float c0 = g_cos[cbase + d],     sn0 = g_sin[cbase + d];
                    float c1 = g_cos[cbase + d + 1], sn1 = g_sin[cbase + d + 1];
                    float t1a = acc[i][j][hf * 2],     t1b = acc[i][j][hf * 2 + 1];
                    float t2a = acc[i][j + 4][hf * 2], t2b = acc[i][j + 4][hf * 2 + 1];
                    float ra  = qscale * (t1a * c0 - t2a * sn0);
                    float rb  = qscale * (t1b * c1 - t2b * sn1);
                    float r2a = qscale * (t1a * sn0 + t2a * c0);
                    float r2b = qscale * (t1b * sn1 + t2b * c1);
                    *(uint32_t*)&dst[baseo + d]      = pack_h(ra, rb);
                    *(uint32_t*)&dst[baseo + d + 32] = pack_h(r2a, r2b);
                }
            }
    }
}

// ==================== Flash attention: BQ=128, BKV=64, exp2 (MUFU) softmax ====================
#define FT     9216
#define FBUF   (2 * FT)
#define SMEM_F (2 * FBUF)

__global__ __launch_bounds__(256, 2) void flash_mma_kernel()
{
    extern __shared__ __align__(128) char fsm[];
    uint32_t sbase = smem_u32(fsm);
    int tid = threadIdx.x, lane = tid & 31, w = tid >> 5;
    int qt = blockIdx.x, bh = blockIdx.y;
    int b = bh >> 4, h = bh & 15;

    const __half* Q  = g_q  + ((size_t)bh * SS + qt * 128) * DD;
    const __half* K  = g_k  + (size_t)bh * SS * DD;
    const __half* Vt = g_vt + (size_t)bh * DD * SS;

    int arow = lane & 15, acg = lane >> 4;
    int brow = (lane & 7) + ((lane >> 4) << 3), bcg = (lane >> 3) & 1;

    #pragma unroll
    for (int it = 0; it < 4; it++) {
        int lin = it * 256 + tid;
        int r = lin >> 3, seg = lin & 7;
        cp_async16(sbase + r * 144 + seg * 16, Q + (size_t)r * DD + seg * 8);
    }
    cp_commit();
    asm volatile("cp.async.wait_group 0;" ::: "memory");
    __syncthreads();
    uint32_t aq[4][4];
    #pragma unroll
    for (int kb = 0; kb < 4; kb++)
        ldsm_x4(aq[kb], sbase + ((w * 16 + arow) * 72 + kb * 16 + acg * 8) * 2);
    __syncthreads();

    float s[8][4], o[8][4];
    #pragma unroll
    for (int j = 0; j < 8; j++)
        #pragma unroll
        for (int q = 0; q < 4; q++) o[j][q] = 0.f;
    float m0 = -1e30f, m1 = -1e30f, l0 = 0.f, l1 = 0.f;

    {
        #pragma unroll
        for (int it = 0; it < 4; it++) {
            int lin = it * 256 + tid;
            int tile = lin >> 9, idx = lin & 511;
            int r = idx >> 3, seg = idx & 7;
            const __half* src = (tile == 0) ? K  + (size_t)r * DD + seg * 8
                                            : Vt + (size_t)r * SS + seg * 8;
            cp_async16(sbase + tile * FT + r * 144 + seg * 16, src);
        }
        cp_commit();
    }

    for (int c = 0; c < 32; c++) {
        if (c + 1 < 32) {
            int kbase = (c + 1) * 64;
            uint32_t sb = sbase + ((c + 1) & 1) * FBUF;
            #pragma unroll
            for (int it = 0; it < 4; it++) {
                int lin = it * 256 + tid;
                int tile = lin >> 9, idx = lin & 511;
                int r = idx >> 3, seg = idx & 7;
                const __half* src = (tile == 0) ? K  + (size_t)(kbase + r) * DD + seg * 8
                                                : Vt + (size_t)r * SS + kbase + seg * 8;
                cp_async16(sb + tile * FT + r * 144 + seg * 16, src);
            }
            cp_commit();
            asm volatile("cp.async.wait_group 1;" ::: "memory");
        } else {
            asm volatile("cp.async.wait_group 0;" ::: "memory");
        }
        __syncthreads();

        uint32_t sb = sbase + (c & 1) * FBUF;

        #pragma unroll
        for (int j = 0; j < 8; j++) { s[j][0] = s[j][1] = s[j][2] = s[j][3] = 0.f; }
        #pragma unroll
        for (int kb = 0; kb < 4; kb++) {
            uint32_t kh[4][4];
            #pragma unroll
            for (int j = 0; j < 4; j++)
                ldsm_x4(kh[j], sb + ((j * 16 + brow) * 72 + kb * 16 + bcg * 8) * 2);
            #pragma unroll
            for (int j = 0; j < 8; j++)
                mma16816(s[j], aq[kb], kh[j >> 1][(j & 1) * 2], kh[j >> 1][(j & 1) * 2 + 1]);
        }

        // ---- online softmax, log2 domain, hardware EX2 ----
        float mx0 = s[0][0], mx1 = s[0][2];
        #pragma unroll
        for (int j = 0; j < 8; j++) {
            mx0 = fmaxf(mx0, fmaxf(s[j][0], s[j][1]));
            mx1 = fmaxf(mx1, fmaxf(s[j][2], s[j][3]));
        }
        mx0 = fmaxf(mx0, __shfl_xor_sync(0xffffffffu, mx0, 1));
        mx0 = fmaxf(mx0, __shfl_xor_sync(0xffffffffu, mx0, 2));
        mx1 = fmaxf(mx1, __shfl_xor_sync(0xffffffffu, mx1, 1));
        mx1 = fmaxf(mx1, __shfl_xor_sync(0xffffffffu, mx1, 2));
        float mn0 = fmaxf(m0, mx0), mn1 = fmaxf(m1, mx1);
        float al0 = hexp2(m0 - mn0), al1 = hexp2(m1 - mn1);
        m0 = mn0; m1 = mn1;
        float sum0 = 0.f, sum1 = 0.f;
        #pragma unroll
        for (int j = 0; j < 8; j++) {
            s[j][0] = hexp2(s[j][0] - mn0);
            s[j][1] = hexp2(s[j][1] - mn0);
            s[j][2] = hexp2(s[j][2] - mn1);
            s[j][3] = hexp2(s[j][3] - mn1);
            sum0 += s[j][0] + s[j][1];
            sum1 += s[j][2] + s[j][3];
        }
        sum0 += __shfl_xor_sync(0xffffffffu, sum0, 1);
        sum0 += __shfl_xor_sync(0xffffffffu, sum0, 2);
        sum1 += __shfl_xor_sync(0xffffffffu, sum1, 1);
        sum1 += __shfl_xor_sync(0xffffffffu, sum1, 2);
        l0 = l0 * al0 + sum0;
        l1 = l1 * al1 + sum1;
        #pragma unroll
        for (int j = 0; j < 8; j++) {
            o[j][0] *= al0; o[j][1] *= al0; o[j][2] *= al1; o[j][3] *= al1;
        }

        #pragma unroll
        for (int kb = 0; kb < 4; kb++) {
            uint32_t ph[4];
            ph[0] = pack_h(s[2 * kb][0],     s[2 * kb][1]);
            ph[1] = pack_h(s[2 * kb][2],     s[2 * kb][3]);
            ph[2] = pack_h(s[2 * kb + 1][0], s[2 * kb + 1][1]);
            ph[3] = pack_h(s[2 * kb + 1][2], s[2 * kb + 1][3]);

            uint32_t vh[4][4];
            #pragma unroll
            for (int j = 0; j < 4; j++)
                ldsm_x4(vh[j], sb + FT + ((j * 16 + brow) * 72 + kb * 16 + bcg * 8) * 2);
            #pragma unroll
            for (int j = 0; j < 8; j++)
                mma16816(o[j], ph, vh[j >> 1][(j & 1) * 2], vh[j >> 1][(j & 1) * 2 + 1]);
        }
        __syncthreads();
    }

    float i0 = 1.f / l0, i1 = 1.f / l1;
    int r0 = qt * 128 + w * 16 + (lane >> 2);
    #pragma unroll
    for (int j = 0; j < 8; j++) {
        int n = h * 64 + j * 8 + (lane & 3) * 2;
        size_t o0 = ((size_t)(b * SS) + r0) * HID + n;
        size_t o1 = o0 + 8 * HID;
        *(uint32_t*)&g_ah[o0] = pack_h(o[j][0] * i0, o[j][1] * i0);
        *(uint32_t*)&g_ah[o1] = pack_h(o[j][2] * i1, o[j][3] * i1);
    }
}

// ==================== launch (resource-disjoint overlap; repo_finish also hidden) ====
extern "C" void kernel_launch(void* const* d_in, const int* in_sizes, int n_in,
                              void* d_out, int out_size)
{
    const float* x  = (const float*)d_in[0];
    const float* Wq = (const float*)d_in[1];
    const float* Wk = (const float*)d_in[2];
    const float* Wv = (const float*)d_in[3];
    const float* Wo = (const float*)d_in[4];
    const float* W1 = (const float*)d_in[5];
    const float* b1 = (const float*)d_in[6];
    const float* W2 = (const float*)d_in[7];
    const float* b2 = (const float*)d_in[8];
    float* out = (float*)d_out;

    cudaFuncSetAttribute(mm_mma_kernel<0>, cudaFuncAttributeMaxDynamicSharedMemorySize, SMEM_MM);
    cudaFuncSetAttribute(mm_mma_kernel<1>, cudaFuncAttributeMaxDynamicSharedMemorySize, SMEM_MM);
    cudaFuncSetAttribute(mm_mma_kernel<2>, cudaFuncAttributeMaxDynamicSharedMemorySize, SMEM_MM);
    cudaFuncSetAttribute(flash_mma_kernel, cudaFuncAttributeMaxDynamicSharedMemorySize, SMEM_F);
    cudaFuncSetAttribute(repo_gemm_kernel, cudaFuncAttributeMaxDynamicSharedMemorySize, RG_SMEM);

    // Per-call stream/events, intentionally leaked (destroying capture-participating
    // resources can invalidate the graph; kernel_launch runs only a few times).
    cudaStream_t s2;
    cudaStreamCreateWithFlags(&s2, cudaStreamNonBlocking);
    cudaEvent_t e0, e1, e2, e3;
    cudaEventCreateWithFlags(&e0, cudaEventDisableTiming);
    cudaEventCreateWithFlags(&e1, cudaEventDisableTiming);
    cudaEventCreateWithFlags(&e2, cudaEventDisableTiming);
    cudaEventCreateWithFlags(&e3, cudaEventDisableTiming);

    // fork 1: conv_x (s2, memory-bound) || conv_wT (main, memory-bound)
    cudaEventRecord(e0, 0);
    cudaStreamWaitEvent(s2, e0, 0);
    conv_x_kernel<<<4096, 256, 0, s2>>>(x);
    cudaEventRecord(e1, s2);
    conv_wT_kernel<<<dim3(32, 32, 5), dim3(32, 32)>>>(Wq, Wk, Wv, Wo, W1);
    cudaStreamWaitEvent(0, e1, 0);

    // serial: repo stage-1 GEMM (tensor-bound; must not overlap other tensor work)
    repo_gemm_kernel<<<dim3(4, 32), 256, RG_SMEM>>>();

    // fork 2: repo_finish -> scan -> angles (s2, non-tensor, ~13us)
    //         || V-GEMM (main, tensor-bound, ~28us)
    cudaEventRecord(e2, 0);
    cudaStreamWaitEvent(s2, e2, 0);
    repo_finish_kernel<<<1024, 128, 0, s2>>>(b1, W2, b2);
    scan_kernel<<<2, 1024, 0, s2>>>();
    angles_kernel<<<512, 256, 0, s2>>>();
    cudaEventRecord(e3, s2);

    mm_mma_kernel<2><<<dim3(8, 32), 256, SMEM_MM>>>(nullptr);     // V projection (no RoPE dep)
    cudaStreamWaitEvent(0, e3, 0);                                // join: angles ready

    mm_mma_kernel<0><<<dim3(8, 32, 2), 256, SMEM_MM>>>(nullptr);  // Q/K with fused RoPE
    flash_mma_kernel<<<dim3(16, 32), 256, SMEM_F>>>();
    mm_mma_kernel<1><<<dim3(8, 32), 256, SMEM_MM>>>(out);
}